// round 12
// baseline (speedup 1.0000x reference)
#include <cuda_runtime.h>
#include <cuda_fp16.h>
#include <cstdint>

// ---------------------------------------------------------------------------
// B=2,S=2048,D=1024,H=16,HD=64, scale=32. softmax over batch (B=2) ==
//   P     = sigmoid((Q0K0^T - Q1K1^T)/32)   per head [2048x2048]
//   vals0 = P @ V0 ;  vals1 = colsum(V1) - P @ V1
// GEMMs: QK proj fp16 3-term | score int8 3-plane 6-pass IMMA |
//        V proj, PV, out: fp16 1-term
// ---------------------------------------------------------------------------

__device__ __align__(128) __half g_xhi[4096 * 1024];
__device__ __align__(128) __half g_xlo[4096 * 1024];
__device__ __align__(128) __half g_wThi[4 * 1024 * 1024];   // [z][n][k]
__device__ __align__(128) __half g_wTlo[4 * 1024 * 1024];
__device__ __align__(128) char  g_Qi8[3][(size_t)16 * 2048 * 128]; // int8 planes
__device__ __align__(128) char  g_Ki8[3][(size_t)16 * 2048 * 128]; // K1 negated
__device__ __align__(128) __half g_V16[16 * 2048 * 128];    // fp16 V [h][s][b*64+d]
__device__ __align__(128) __half g_Vthi[16 * 128 * 2048];   // [h][b*64+d][s]
__device__ __align__(128) __half g_P[(size_t)16 * 2048 * 2048];
__device__ __align__(128) __half g_Valshi[4096 * 1024];     // [b*2048+q][h*64+d]
__device__ float g_ColPart[16 * 16 * 64];
__device__ float g_Colsum[16 * 64];

#define SSTR   40                 // halfs per smem row, 32-K chunks (+8 pad)
#define PLANEH (128 * SSTR)       // 5120 halfs / 10240 B
#define SW128B(x) ((x) ^ (((x) >> 3) & 0x70))

// ---------------------------------------------------------------------------
static __device__ __forceinline__ void cpa16(const void* dst_smem, const void* src) {
    uint32_t d = (uint32_t)__cvta_generic_to_shared(dst_smem);
    asm volatile("cp.async.cg.shared.global [%0], [%1], 16;" :: "r"(d), "l"(src));
}
static __device__ __forceinline__ void ldm4(uint32_t r[4], const void* p) {
    uint32_t a = (uint32_t)__cvta_generic_to_shared(p);
    asm volatile("ldmatrix.sync.aligned.m8n8.x4.shared.b16 {%0,%1,%2,%3}, [%4];"
                 : "=r"(r[0]), "=r"(r[1]), "=r"(r[2]), "=r"(r[3]) : "r"(a));
}
static __device__ __forceinline__ void mma16816(float c[4], const uint32_t a[4],
                                                uint32_t b0, uint32_t b1) {
    asm volatile(
        "mma.sync.aligned.m16n8k16.row.col.f32.f16.f16.f32 "
        "{%0,%1,%2,%3}, {%4,%5,%6,%7}, {%8,%9}, {%0,%1,%2,%3};"
        : "+f"(c[0]), "+f"(c[1]), "+f"(c[2]), "+f"(c[3])
        : "r"(a[0]), "r"(a[1]), "r"(a[2]), "r"(a[3]), "r"(b0), "r"(b1));
}
static __device__ __forceinline__ void imma16832(int c[4], const uint32_t a[4],
                                                 uint32_t b0, uint32_t b1) {
    asm volatile(
        "mma.sync.aligned.m16n8k32.row.col.s32.s8.s8.s32 "
        "{%0,%1,%2,%3}, {%4,%5,%6,%7}, {%8,%9}, {%0,%1,%2,%3};"
        : "+r"(c[0]), "+r"(c[1]), "+r"(c[2]), "+r"(c[3])
        : "r"(a[0]), "r"(a[1]), "r"(a[2]), "r"(a[3]), "r"(b0), "r"(b1));
}
static __device__ __forceinline__ void splitstore(__half* hp, __half* lp,
                                                  float v0, float v1) {
    __half h0 = __float2half_rn(v0), h1 = __float2half_rn(v1);
    *(__half2*)hp = __halves2half2(h0, h1);
    *(__half2*)lp = __halves2half2(__float2half_rn(v0 - __half2float(h0)),
                                   __float2half_rn(v1 - __half2float(h1)));
}
// decompose round(v*2^15) into 3 signed-8 digits (base 256); rare clamp ok
static __device__ __forceinline__ void dec3(float v, int& a0, int& a1, int& a2) {
    int iq = __float2int_rn(v * 32768.f);
    a0 = (iq + 32768) >> 16;
    int r = iq - (a0 << 16);
    a1 = (r + 128) >> 8;
    if (a1 > 127) a1 = 127;
    a2 = r - (a1 << 8);
    if (a2 > 127) a2 = 127;
}

enum { EPI_QK = 0, EPI_V, EPI_PV, EPI_OUT };

// ---------------------------------------------------------------------------
// 128x128 NT GEMM, fp16 mma + ldmatrix, NSTG-stage cp.async, fused epilogue.
// NTERM=3: Ahi*Bhi + Alo*Bhi + Ahi*Blo ; NTERM=1: A*Bhi
// ---------------------------------------------------------------------------
template <int KTOT, int NTERM, int EPI, int OCC, int NSTG>
__global__ __launch_bounds__(256, OCC) void gemm_kernel(float* outp)
{
    extern __shared__ __align__(128) __half sm[];
    const int NA = (NTERM == 3) ? 2 : 1;
    const int NB = (NTERM >= 2) ? 2 : 1;
    const int NT = NA + NB;

    const int tid = threadIdx.x, warp = tid >> 5, lane = tid & 31;
    const int wm = (warp & 3) * 32, wn = (warp >> 2) * 64;
    const int m0 = blockIdx.y * 128, n0 = blockIdx.x * 128, z = blockIdx.z;

    const __half *Ahi, *Alo = nullptr, *Bhi, *Blo = nullptr;
    int lda, ldb;
    if (EPI == EPI_QK) {
        Ahi = g_xhi; Alo = g_xlo; lda = 1024;
        Bhi = g_wThi + (size_t)z * 1048576; Blo = g_wTlo + (size_t)z * 1048576; ldb = 1024;
    } else if (EPI == EPI_V) {
        Ahi = g_xhi; lda = 1024;
        Bhi = g_wThi + (size_t)2 * 1048576; ldb = 1024;
    } else if (EPI == EPI_PV) {
        Ahi = g_P + (size_t)z * 2048 * 2048; lda = 2048;
        Bhi = g_Vthi + (size_t)z * 128 * 2048; ldb = 2048;
    } else {
        Ahi = g_Valshi; lda = 1024;
        Bhi = g_wThi + (size_t)3 * 1048576; ldb = 1024;
    }

    auto plane = [&](int st, int pl) -> __half* { return sm + (st * NT + pl) * PLANEH; };

    auto load_stage = [&](int ch) {
        const int st = ch % NSTG, k0 = ch * 32;
#pragma unroll
        for (int r = 0; r < 2; ++r) {
            const int idx = tid + r * 256;
            const int row = idx >> 2, col = (idx & 3) * 8;
            cpa16(plane(st, 0) + row * SSTR + col, Ahi + (size_t)(m0 + row) * lda + k0 + col);
            if (NA == 2)
                cpa16(plane(st, 1) + row * SSTR + col, Alo + (size_t)(m0 + row) * lda + k0 + col);
            cpa16(plane(st, NA) + row * SSTR + col, Bhi + (size_t)(n0 + row) * ldb + k0 + col);
            if (NB == 2)
                cpa16(plane(st, NA + 1) + row * SSTR + col, Blo + (size_t)(n0 + row) * ldb + k0 + col);
        }
        asm volatile("cp.async.commit_group;" ::: "memory");
    };

    float c[2][8][4] = {};
    const int nCh = KTOT / 32;
    load_stage(0);
    if (NSTG == 3 && nCh > 1) load_stage(1);

    const int lrow = lane & 15, lkh = (lane >> 4) * 8;

    for (int ch = 0; ch < nCh; ++ch) {
        if (NSTG == 3) {
            if (ch + 1 < nCh) asm volatile("cp.async.wait_group 1;" ::: "memory");
            else              asm volatile("cp.async.wait_group 0;" ::: "memory");
            __syncthreads();
            if (ch + 2 < nCh) load_stage(ch + 2);
        } else {
            if (ch + 1 < nCh) {
                __syncthreads();
                load_stage(ch + 1);
                asm volatile("cp.async.wait_group 1;" ::: "memory");
            } else {
                asm volatile("cp.async.wait_group 0;" ::: "memory");
            }
            __syncthreads();
        }
        const int buf = ch % NSTG;

#pragma unroll
        for (int s = 0; s < 2; ++s) {
            const int ks = s * 16;
            uint32_t a[2][2][4];
#pragma unroll
            for (int pa = 0; pa < NA; ++pa)
#pragma unroll
                for (int mt = 0; mt < 2; ++mt)
                    ldm4(a[pa][mt], plane(buf, pa) + (wm + mt * 16 + lrow) * SSTR + ks + lkh);

            uint32_t bh[4][4];
#pragma unroll
            for (int np = 0; np < 4; ++np) {
                ldm4(bh[np], plane(buf, NA) + (wn + np * 16 + lrow) * SSTR + ks + lkh);
#pragma unroll
                for (int mt = 0; mt < 2; ++mt) {
                    mma16816(c[mt][2 * np],     a[0][mt], bh[np][0], bh[np][2]);
                    mma16816(c[mt][2 * np + 1], a[0][mt], bh[np][1], bh[np][3]);
                }
            }
            if (NA == 2) {
#pragma unroll
                for (int np = 0; np < 4; ++np)
#pragma unroll
                    for (int mt = 0; mt < 2; ++mt) {
                        mma16816(c[mt][2 * np],     a[1][mt], bh[np][0], bh[np][2]);
                        mma16816(c[mt][2 * np + 1], a[1][mt], bh[np][1], bh[np][3]);
                    }
            }
            if (NB == 2) {
#pragma unroll
                for (int np = 0; np < 4; ++np) {
                    uint32_t bl[4];
                    ldm4(bl, plane(buf, NA + 1) + (wn + np * 16 + lrow) * SSTR + ks + lkh);
#pragma unroll
                    for (int mt = 0; mt < 2; ++mt) {
                        mma16816(c[mt][2 * np],     a[0][mt], bl[0], bl[2]);
                        mma16816(c[mt][2 * np + 1], a[0][mt], bl[1], bl[3]);
                    }
                }
            }
        }
    }

    // ---- epilogue: m = m0+wm+mt*16+lane/4+p*8 ; n = n0+wn+nt*8+(lane%4)*2 ----
#pragma unroll
    for (int mt = 0; mt < 2; ++mt)
#pragma unroll
        for (int nt = 0; nt < 8; ++nt)
#pragma unroll
            for (int p = 0; p < 2; ++p) {
                const int m = m0 + wm + mt * 16 + (lane >> 2) + p * 8;
                const int nl = wn + nt * 8 + (lane & 3) * 2;
                float v0 = c[mt][nt][2 * p], v1 = c[mt][nt][2 * p + 1];

                if (EPI == EPI_QK) {
                    const int b = m >> 11, s = m & 2047;
                    const int n = n0 + nl, h = n >> 6, d = n & 63;
                    const size_t base = ((size_t)(h * 2048 + s)) * 128 + b * 64 + d;
                    if (z == 1 && b == 1) { v0 = -v0; v1 = -v1; }
                    int x0, x1, x2, y0, y1, y2;
                    dec3(v0, x0, x1, x2);
                    dec3(v1, y0, y1, y2);
                    char* p0 = (z == 0) ? g_Qi8[0] : g_Ki8[0];
                    char* p1 = (z == 0) ? g_Qi8[1] : g_Ki8[1];
                    char* p2 = (z == 0) ? g_Qi8[2] : g_Ki8[2];
                    *(char2*)&p0[base] = make_char2((char)x0, (char)y0);
                    *(char2*)&p1[base] = make_char2((char)x1, (char)y1);
                    *(char2*)&p2[base] = make_char2((char)x2, (char)y2);
                } else if (EPI == EPI_V) {
                    const int b = m >> 11, s = m & 2047;
                    const int n = n0 + nl, h = n >> 6, d = n & 63;
                    *(__half2*)&g_V16[((size_t)(h * 2048 + s)) * 128 + b * 64 + d] =
                        __floats2half2_rn(v0, v1);
                } else if (EPI == EPI_PV) {
                    const int b = nl >> 6, d = nl & 63;
                    if (b) {
                        v0 = g_Colsum[z * 64 + d]     - v0;
                        v1 = g_Colsum[z * 64 + d + 1] - v1;
                    }
                    *(__half2*)&g_Valshi[((size_t)(b * 2048 + m)) * 1024 + z * 64 + d] =
                        __floats2half2_rn(v0, v1);
                } else {
                    *(float2*)&outp[(size_t)m * 1024 + n0 + nl] = make_float2(v0, v1);
                }
            }
}

// ---------------------------------------------------------------------------
// Score (int8 IMMA): S = 4*acc0 + 2^-6*acc1 + 2^-14*acc2 ; P = sigmoid(S/32).
// Q (3 planes, 64x128B) resident; K streamed 2-stage over 16 n-tiles.
// 128 threads = 4 warps (2m x 2n), warp 32x32, 3 CTAs/SM.
// Grid (2, 32, 16) = (n-half, m-tile, head).
// ---------------------------------------------------------------------------
__global__ __launch_bounds__(128, 3) void score_i8_kernel()
{
    extern __shared__ __align__(128) char smc[];
    auto qpl = [&](int p) -> char* { return smc + p * 8192; };
    auto kpl = [&](int st, int p) -> char* { return smc + 24576 + (st * 3 + p) * 8192; };

    const int tid = threadIdx.x, warp = tid >> 5, lane = tid & 31;
    const int wm = (warp & 1) * 32, wn = (warp >> 1) * 32;
    const int h = blockIdx.z, m0 = blockIdx.y * 64, nbase = blockIdx.x * 1024;

    // resident Q: 3 planes x 64 rows x 128 B (SW128 swizzled)
#pragma unroll
    for (int p = 0; p < 3; ++p)
#pragma unroll
        for (int r = 0; r < 4; ++r) {
            const int idx = tid + r * 128;
            const int row = idx >> 3, col = (idx & 7) * 16;
            cpa16(qpl(p) + SW128B(row * 128 + col),
                  g_Qi8[p] + ((size_t)(h * 2048 + m0 + row)) * 128 + col);
        }
    asm volatile("cp.async.commit_group;" ::: "memory");

    auto loadK = [&](int nt) {
        const int st = nt & 1;
#pragma unroll
        for (int p = 0; p < 3; ++p)
#pragma unroll
            for (int r = 0; r < 4; ++r) {
                const int idx = tid + r * 128;
                const int row = idx >> 3, col = (idx & 7) * 16;
                cpa16(kpl(st, p) + SW128B(row * 128 + col),
                      g_Ki8[p] + ((size_t)(h * 2048 + nbase + nt * 64 + row)) * 128 + col);
            }
        asm volatile("cp.async.commit_group;" ::: "memory");
    };

    loadK(0);
    int acc[3][2][4][4] = {};   // term, m-tile, n8, frag
    const int lrow = lane & 15, lkb = (lane >> 4) * 16;   // byte col half
    const __half2 one2 = __float2half2_rn(1.0f);
    const float NK = -0.04508422f;   // -log2(e)/32

    const int NTl = 16;
    for (int nt = 0; nt < NTl; ++nt) {
        if (nt + 1 < NTl) {
            __syncthreads();
            loadK(nt + 1);
            asm volatile("cp.async.wait_group 1;" ::: "memory");
        } else {
            asm volatile("cp.async.wait_group 0;" ::: "memory");
        }
        __syncthreads();
        const int st = nt & 1;

#pragma unroll
        for (int ks = 0; ks < 4; ++ks) {
            const int kb = ks * 32 + lkb;
            uint32_t a[3][2][4];
#pragma unroll
            for (int p = 0; p < 3; ++p)
#pragma unroll
                for (int mt = 0; mt < 2; ++mt)
                    ldm4(a[p][mt], qpl(p) + SW128B((wm + mt * 16 + lrow) * 128 + kb));

#pragma unroll
            for (int pb = 0; pb < 3; ++pb)
#pragma unroll
                for (int nn = 0; nn < 2; ++nn) {
                    uint32_t b[4];
                    ldm4(b, kpl(st, pb) + SW128B((wn + nn * 16 + lrow) * 128 + kb));
#pragma unroll
                    for (int pa = 0; pa < 3; ++pa) {
                        if (pa + pb > 2) continue;   // keep terms with weight >= 2^16
                        const int t = pa + pb;
#pragma unroll
                        for (int mt = 0; mt < 2; ++mt) {
                            imma16832(acc[t][mt][2 * nn],     a[pa][mt], b[0], b[2]);
                            imma16832(acc[t][mt][2 * nn + 1], a[pa][mt], b[1], b[3]);
                        }
                    }
                }
        }

        // epilogue for this 64x64 n-tile
#pragma unroll
        for (int mt = 0; mt < 2; ++mt)
#pragma unroll
            for (int j = 0; j < 4; ++j)
#pragma unroll
                for (int p = 0; p < 2; ++p) {
                    const int m = m0 + wm + mt * 16 + (lane >> 2) + p * 8;
                    const int n = nbase + nt * 64 + wn + j * 8 + (lane & 3) * 2;
                    float f0 = fmaf(6.103515625e-5f, (float)acc[2][mt][j][2 * p],
                               fmaf(0.015625f, (float)acc[1][mt][j][2 * p],
                                    4.0f * (float)acc[0][mt][j][2 * p]));
                    float f1 = fmaf(6.103515625e-5f, (float)acc[2][mt][j][2 * p + 1],
                               fmaf(0.015625f, (float)acc[1][mt][j][2 * p + 1],
                                    4.0f * (float)acc[0][mt][j][2 * p + 1]));
                    __half2 m2 = __floats2half2_rn(f0 * NK, f1 * NK);
                    __half2 P2 = h2rcp(__hadd2(one2, h2exp2(m2)));
                    *(__half2*)&g_P[((size_t)h * 2048 + m) * 2048 + n] = P2;
#pragma unroll
                    for (int t = 0; t < 3; ++t) {
                        acc[t][mt][j][2 * p] = 0;
                        acc[t][mt][j][2 * p + 1] = 0;
                    }
                }
    }
}

// ---------------------------------------------------------------------------
// prep kernels
// ---------------------------------------------------------------------------
__global__ __launch_bounds__(256) void split_x_kernel(const float* __restrict__ x)
{
    const size_t i = ((size_t)blockIdx.x * 256 + threadIdx.x) * 4;
    float4 v = *(const float4*)(x + i);
    splitstore(&g_xhi[i],     &g_xlo[i],     v.x, v.y);
    splitstore(&g_xhi[i + 2], &g_xlo[i + 2], v.z, v.w);
}

__global__ __launch_bounds__(256) void trw_kernel(
    const float* __restrict__ w0, const float* __restrict__ w1,
    const float* __restrict__ w2, const float* __restrict__ w3)
{
    const float* W = (blockIdx.z == 0) ? w0 : (blockIdx.z == 1) ? w1
                     : (blockIdx.z == 2) ? w2 : w3;
    __shared__ float t[32][33];
    const int bx = blockIdx.x * 32, by = blockIdx.y * 32;
    const int tx = threadIdx.x & 31, ty8 = threadIdx.x >> 5;
#pragma unroll
    for (int s = 0; s < 4; ++s)
        t[ty8 + s * 8][tx] = W[(size_t)(by + ty8 + s * 8) * 1024 + bx + tx];
    __syncthreads();
    __half* Dh = g_wThi + (size_t)blockIdx.z * 1048576;
    __half* Dl = g_wTlo + (size_t)blockIdx.z * 1048576;
#pragma unroll
    for (int s = 0; s < 4; ++s) {
        const int ty = ty8 + s * 8;
        const float v = t[tx][ty];
        const size_t o = (size_t)(bx + ty) * 1024 + by + tx;
        __half h = __float2half_rn(v);
        Dh[o] = h;
        Dl[o] = __float2half_rn(v - __half2float(h));
    }
}

// transpose V per (head, 128-s-chunk) + deterministic colsum partials of V1
__global__ __launch_bounds__(256) void trv_kernel()
{
    extern __shared__ float tl[];   // [128][129]
    const int sc = blockIdx.x, h = blockIdx.y;
    const int s0 = sc * 128;
    const __half* V = g_V16 + ((size_t)h * 2048 + s0) * 128;

    for (int i = threadIdx.x; i < 128 * 128; i += 256)
        tl[(i >> 7) * 129 + (i & 127)] = __half2float(V[i]);
    __syncthreads();

    if (threadIdx.x < 64) {
        float acc = 0.f;
        for (int s = 0; s < 128; ++s) acc += tl[s * 129 + 64 + threadIdx.x];
        g_ColPart[((size_t)h * 16 + sc) * 64 + threadIdx.x] = acc;
    }

    const int dp = threadIdx.x & 127, seg = threadIdx.x >> 7;
    __half* Th = g_Vthi + ((size_t)h * 128 + dp) * 2048 + s0 + seg * 64;
#pragma unroll 8
    for (int j = 0; j < 64; ++j)
        Th[j] = __float2half_rn(tl[(seg * 64 + j) * 129 + dp]);
}

__global__ void redc_kernel()
{
    const int t = threadIdx.x;   // 1024 = 16h * 64d
    const int h = t >> 6, d = t & 63;
    float a = 0.f;
    for (int sc = 0; sc < 16; ++sc)
        a += g_ColPart[((size_t)h * 16 + sc) * 64 + d];
    g_Colsum[t] = a;
}

// ---------------------------------------------------------------------------
extern "C" void kernel_launch(void* const* d_in, const int* in_sizes, int n_in,
                              void* d_out, int out_size)
{
    const float* x  = (const float*)d_in[0];
    const float* wq = (const float*)d_in[1];
    const float* wk = (const float*)d_in[2];
    const float* wv = (const float*)d_in[3];
    const float* wo = (const float*)d_in[4];
    float* out = (float*)d_out;

    const int PB    = PLANEH * 2;                 // 10240 B / plane
    const int SM_QK = 2 * 4 * PB;                 //  81920 (3-term, 2-stage)
    const int SM_1T = 3 * 2 * PB;                 //  61440 (1-term, 3-stage)
    const int SM_SC = 24576 + 6 * 8192;           //  73728 (score int8)
    const int SMT   = 128 * 129 * 4;              //  66048

    cudaFuncSetAttribute(gemm_kernel<1024, 3, EPI_QK,  2, 2>, cudaFuncAttributeMaxDynamicSharedMemorySize, SM_QK);
    cudaFuncSetAttribute(gemm_kernel<1024, 1, EPI_V,   2, 3>, cudaFuncAttributeMaxDynamicSharedMemorySize, SM_1T);
    cudaFuncSetAttribute(gemm_kernel<2048, 1, EPI_PV,  2, 3>, cudaFuncAttributeMaxDynamicSharedMemorySize, SM_1T);
    cudaFuncSetAttribute(gemm_kernel<1024, 1, EPI_OUT, 2, 3>, cudaFuncAttributeMaxDynamicSharedMemorySize, SM_1T);
    cudaFuncSetAttribute(score_i8_kernel, cudaFuncAttributeMaxDynamicSharedMemorySize, SM_SC);
    cudaFuncSetAttribute(trv_kernel,      cudaFuncAttributeMaxDynamicSharedMemorySize, SMT);

    split_x_kernel<<<4096, 256>>>(x);
    trw_kernel<<<dim3(32, 32, 4), 256>>>(wq, wk, wv, wo);

    gemm_kernel<1024, 3, EPI_QK, 2, 2><<<dim3(8, 32, 2), 256, SM_QK>>>(nullptr);
    gemm_kernel<1024, 1, EPI_V,  2, 3><<<dim3(8, 32, 1), 256, SM_1T>>>(nullptr);

    trv_kernel<<<dim3(16, 16), 256, SMT>>>();
    redc_kernel<<<1, 1024>>>();

    score_i8_kernel<<<dim3(2, 32, 16), 128, SM_SC>>>();
    gemm_kernel<2048, 1, EPI_PV, 2, 3><<<dim3(1, 16, 16), 256, SM_1T>>>(nullptr);
    gemm_kernel<1024, 1, EPI_OUT, 2, 3><<<dim3(8, 32, 1), 256, SM_1T>>>(out);
}

// round 13
// speedup vs baseline: 2.0422x; 2.0422x over previous
#include <cuda_runtime.h>
#include <cuda_fp16.h>
#include <cstdint>

// ---------------------------------------------------------------------------
// B=2,S=2048,D=1024,H=16,HD=64, scale=32. softmax over batch (B=2) ==
//   P     = sigmoid((Q0K0^T - Q1K1^T)/32)   per head [2048x2048]
//   vals0 = P @ V0 ;  vals1 = colsum(V1) - P @ V1
// fp16 mma.sync m16n8k16 NT GEMMs; hi/lo split planes:
//   Q/K proj: 3-term | score: 3-term fused with PV (flash-style, P in regs) |
//   V proj, out: 1-term
// ---------------------------------------------------------------------------

__device__ __align__(128) __half g_xhi[4096 * 1024];
__device__ __align__(128) __half g_xlo[4096 * 1024];
__device__ __align__(128) __half g_wThi[4 * 1024 * 1024];   // [z][n][k]
__device__ __align__(128) __half g_wTlo[4 * 1024 * 1024];
__device__ __align__(128) __half g_Qhi[16 * 2048 * 128];    // [h][s][b*64+d]
__device__ __align__(128) __half g_Qlo[16 * 2048 * 128];
__device__ __align__(128) __half g_Khi[16 * 2048 * 128];    // K1 negated
__device__ __align__(128) __half g_Klo[16 * 2048 * 128];
__device__ __align__(128) __half g_V16[16 * 2048 * 128];    // fp16 V [h][s][b*64+d]
__device__ __align__(128) __half g_Vthi[16 * 128 * 2048];   // [h][b*64+d][s]
__device__ __align__(128) __half g_Valshi[4096 * 1024];     // [b*2048+q][h*64+d]
__device__ float g_ColPart[16 * 16 * 64];
__device__ float g_Colsum[16 * 64];

#define SSTR   40                 // halfs per smem row, 32-K chunks (+8 pad)
#define PLANEH (128 * SSTR)       // 5120 halfs / 10240 B
#define ASTR   136                // halfs per row for resident 128-K planes

// ---------------------------------------------------------------------------
static __device__ __forceinline__ void cpa16(const __half* dst_smem, const void* src) {
    uint32_t d = (uint32_t)__cvta_generic_to_shared(dst_smem);
    asm volatile("cp.async.cg.shared.global [%0], [%1], 16;" :: "r"(d), "l"(src));
}
static __device__ __forceinline__ void ldm4(uint32_t r[4], const void* p) {
    uint32_t a = (uint32_t)__cvta_generic_to_shared(p);
    asm volatile("ldmatrix.sync.aligned.m8n8.x4.shared.b16 {%0,%1,%2,%3}, [%4];"
                 : "=r"(r[0]), "=r"(r[1]), "=r"(r[2]), "=r"(r[3]) : "r"(a));
}
static __device__ __forceinline__ void mma16816(float c[4], const uint32_t a[4],
                                                uint32_t b0, uint32_t b1) {
    asm volatile(
        "mma.sync.aligned.m16n8k16.row.col.f32.f16.f16.f32 "
        "{%0,%1,%2,%3}, {%4,%5,%6,%7}, {%8,%9}, {%0,%1,%2,%3};"
        : "+f"(c[0]), "+f"(c[1]), "+f"(c[2]), "+f"(c[3])
        : "r"(a[0]), "r"(a[1]), "r"(a[2]), "r"(a[3]), "r"(b0), "r"(b1));
}
static __device__ __forceinline__ void splitstore(__half* hp, __half* lp,
                                                  float v0, float v1) {
    __half h0 = __float2half_rn(v0), h1 = __float2half_rn(v1);
    *(__half2*)hp = __halves2half2(h0, h1);
    *(__half2*)lp = __halves2half2(__float2half_rn(v0 - __half2float(h0)),
                                   __float2half_rn(v1 - __half2float(h1)));
}
// sigmoid(-S/32) pair -> packed fp16x2 (lo = first value)
static __device__ __forceinline__ uint32_t sig2(float f0, float f1) {
    const float NK = -0.04508422f;   // -log2(e)/32
    __half2 m2 = __floats2half2_rn(f0 * NK, f1 * NK);
    __half2 P2 = h2rcp(__hadd2(__float2half2_rn(1.0f), h2exp2(m2)));
    return *reinterpret_cast<uint32_t*>(&P2);
}

enum { EPI_QK = 0, EPI_V, EPI_OUT };

// ---------------------------------------------------------------------------
// 128x128 NT GEMM, fp16 mma + ldmatrix, NSTG-stage cp.async, fused epilogue.
// NTERM=3: Ahi*Bhi + Alo*Bhi + Ahi*Blo ; NTERM=1: A*Bhi
// ---------------------------------------------------------------------------
template <int KTOT, int NTERM, int EPI, int OCC, int NSTG>
__global__ __launch_bounds__(256, OCC) void gemm_kernel(float* outp)
{
    extern __shared__ __align__(128) __half sm[];
    const int NA = (NTERM == 3) ? 2 : 1;
    const int NB = (NTERM >= 2) ? 2 : 1;
    const int NT = NA + NB;

    const int tid = threadIdx.x, warp = tid >> 5, lane = tid & 31;
    const int wm = (warp & 3) * 32, wn = (warp >> 2) * 64;
    const int m0 = blockIdx.y * 128, n0 = blockIdx.x * 128, z = blockIdx.z;

    const __half *Ahi, *Alo = nullptr, *Bhi, *Blo = nullptr;
    int lda, ldb;
    if (EPI == EPI_QK) {
        Ahi = g_xhi; Alo = g_xlo; lda = 1024;
        Bhi = g_wThi + (size_t)z * 1048576; Blo = g_wTlo + (size_t)z * 1048576; ldb = 1024;
    } else if (EPI == EPI_V) {
        Ahi = g_xhi; lda = 1024;
        Bhi = g_wThi + (size_t)2 * 1048576; ldb = 1024;
    } else {
        Ahi = g_Valshi; lda = 1024;
        Bhi = g_wThi + (size_t)3 * 1048576; ldb = 1024;
    }

    auto plane = [&](int st, int pl) -> __half* { return sm + (st * NT + pl) * PLANEH; };

    auto load_stage = [&](int ch) {
        const int st = ch % NSTG, k0 = ch * 32;
#pragma unroll
        for (int r = 0; r < 2; ++r) {
            const int idx = tid + r * 256;
            const int row = idx >> 2, col = (idx & 3) * 8;
            cpa16(plane(st, 0) + row * SSTR + col, Ahi + (size_t)(m0 + row) * lda + k0 + col);
            if (NA == 2)
                cpa16(plane(st, 1) + row * SSTR + col, Alo + (size_t)(m0 + row) * lda + k0 + col);
            cpa16(plane(st, NA) + row * SSTR + col, Bhi + (size_t)(n0 + row) * ldb + k0 + col);
            if (NB == 2)
                cpa16(plane(st, NA + 1) + row * SSTR + col, Blo + (size_t)(n0 + row) * ldb + k0 + col);
        }
        asm volatile("cp.async.commit_group;" ::: "memory");
    };

    float c[2][8][4] = {};
    const int nCh = KTOT / 32;
    load_stage(0);
    if (NSTG == 3 && nCh > 1) load_stage(1);

    const int lrow = lane & 15, lkh = (lane >> 4) * 8;

    for (int ch = 0; ch < nCh; ++ch) {
        if (NSTG == 3) {
            if (ch + 1 < nCh) asm volatile("cp.async.wait_group 1;" ::: "memory");
            else              asm volatile("cp.async.wait_group 0;" ::: "memory");
            __syncthreads();
            if (ch + 2 < nCh) load_stage(ch + 2);
        } else {
            if (ch + 1 < nCh) {
                __syncthreads();
                load_stage(ch + 1);
                asm volatile("cp.async.wait_group 1;" ::: "memory");
            } else {
                asm volatile("cp.async.wait_group 0;" ::: "memory");
            }
            __syncthreads();
        }
        const int buf = ch % NSTG;

#pragma unroll
        for (int s = 0; s < 2; ++s) {
            const int ks = s * 16;
            uint32_t a[2][2][4];
#pragma unroll
            for (int pa = 0; pa < NA; ++pa)
#pragma unroll
                for (int mt = 0; mt < 2; ++mt)
                    ldm4(a[pa][mt], plane(buf, pa) + (wm + mt * 16 + lrow) * SSTR + ks + lkh);

            uint32_t bh[4][4];
#pragma unroll
            for (int np = 0; np < 4; ++np) {
                ldm4(bh[np], plane(buf, NA) + (wn + np * 16 + lrow) * SSTR + ks + lkh);
#pragma unroll
                for (int mt = 0; mt < 2; ++mt) {
                    mma16816(c[mt][2 * np],     a[0][mt], bh[np][0], bh[np][2]);
                    mma16816(c[mt][2 * np + 1], a[0][mt], bh[np][1], bh[np][3]);
                }
            }
            if (NA == 2) {
#pragma unroll
                for (int np = 0; np < 4; ++np)
#pragma unroll
                    for (int mt = 0; mt < 2; ++mt) {
                        mma16816(c[mt][2 * np],     a[1][mt], bh[np][0], bh[np][2]);
                        mma16816(c[mt][2 * np + 1], a[1][mt], bh[np][1], bh[np][3]);
                    }
            }
            if (NB == 2) {
#pragma unroll
                for (int np = 0; np < 4; ++np) {
                    uint32_t bl[4];
                    ldm4(bl, plane(buf, NA + 1) + (wn + np * 16 + lrow) * SSTR + ks + lkh);
#pragma unroll
                    for (int mt = 0; mt < 2; ++mt) {
                        mma16816(c[mt][2 * np],     a[0][mt], bl[0], bl[2]);
                        mma16816(c[mt][2 * np + 1], a[0][mt], bl[1], bl[3]);
                    }
                }
            }
        }
    }

    // ---- epilogue: m = m0+wm+mt*16+lane/4+p*8 ; n = n0+wn+nt*8+(lane%4)*2 ----
#pragma unroll
    for (int mt = 0; mt < 2; ++mt)
#pragma unroll
        for (int nt = 0; nt < 8; ++nt)
#pragma unroll
            for (int p = 0; p < 2; ++p) {
                const int m = m0 + wm + mt * 16 + (lane >> 2) + p * 8;
                const int nl = wn + nt * 8 + (lane & 3) * 2;
                float v0 = c[mt][nt][2 * p], v1 = c[mt][nt][2 * p + 1];

                if (EPI == EPI_QK) {
                    const int b = m >> 11, s = m & 2047;
                    const int n = n0 + nl, h = n >> 6, d = n & 63;
                    const size_t base = ((size_t)(h * 2048 + s)) * 128 + b * 64 + d;
                    if (z == 1 && b == 1) { v0 = -v0; v1 = -v1; }
                    __half* Dh = (z == 0) ? g_Qhi : g_Khi;
                    __half* Dl = (z == 0) ? g_Qlo : g_Klo;
                    splitstore(&Dh[base], &Dl[base], v0, v1);
                } else if (EPI == EPI_V) {
                    const int b = m >> 11, s = m & 2047;
                    const int n = n0 + nl, h = n >> 6, d = n & 63;
                    *(__half2*)&g_V16[((size_t)(h * 2048 + s)) * 128 + b * 64 + d] =
                        __floats2half2_rn(v0, v1);
                } else {
                    *(float2*)&outp[(size_t)m * 1024 + n0 + nl] = make_float2(v0, v1);
                }
            }
}

// ---------------------------------------------------------------------------
// Fused score+PV (flash style). Per CTA: 64 q-rows of one head.
// Loop over 16 n-tiles (128 keys): S = 3-term QK^T (Q hi/lo resident),
// P = sigmoid(S/32) -> fp16 A-frags in registers, O += P @ Vt (fp32 regs).
// 128 threads = 4 warps, warp = 16 m-rows. smem 96256 B -> occ 2.
// Pipeline: chunk-granular groups, 1 in flight, issue-after-consume.
// ---------------------------------------------------------------------------
__global__ __launch_bounds__(128, 2) void fattn_kernel()
{
    extern __shared__ __align__(128) __half sm[];
    __half* Q0 = sm;                          // 64 x ASTR
    __half* Q1 = Q0 + 64 * ASTR;
    __half* Kb = Q1 + 64 * ASTR;              // [2 slots][2 planes][PLANEH]
    __half* Vb = Kb + 4 * PLANEH;             // [2 slots][PLANEH]
    auto kpl = [&](int slot, int pl) -> __half* { return Kb + (slot * 2 + pl) * PLANEH; };
    auto vpl = [&](int slot) -> __half* { return Vb + slot * PLANEH; };

    const int tid = threadIdx.x, warp = tid >> 5, lane = tid & 31;
    const int h = blockIdx.y, m0 = blockIdx.x * 64;

    const __half* Qh = g_Qhi + ((size_t)h * 2048 + m0) * 128;
    const __half* Ql = g_Qlo + ((size_t)h * 2048 + m0) * 128;
    const __half* Kh = g_Khi + (size_t)h * 2048 * 128;
    const __half* Kl = g_Klo + (size_t)h * 2048 * 128;
    const __half* Vt = g_Vthi + (size_t)h * 128 * 2048;

    // group 0: resident Q (both planes)
#pragma unroll
    for (int r = 0; r < 8; ++r) {
        const int idx = tid + r * 128;
        const int row = idx >> 4, col = (idx & 15) * 8;
        cpa16(Q0 + row * ASTR + col, Qh + row * 128 + col);
        cpa16(Q1 + row * ASTR + col, Ql + row * 128 + col);
    }
    asm volatile("cp.async.commit_group;" ::: "memory");

    auto issueK = [&](int nt, int kc) {   // K chunk: 128 n-rows x 32 d (hi+lo)
        const int slot = kc & 1, k0 = kc * 32;
#pragma unroll
        for (int r = 0; r < 4; ++r) {
            const int idx = tid + r * 128;
            const int row = idx >> 2, col = (idx & 3) * 8;
            const size_t src = (size_t)(nt * 128 + row) * 128 + k0 + col;
            cpa16(kpl(slot, 0) + row * SSTR + col, Kh + src);
            cpa16(kpl(slot, 1) + row * SSTR + col, Kl + src);
        }
        asm volatile("cp.async.commit_group;" ::: "memory");
    };
    auto issueV = [&](int nt, int vc) {   // Vt chunk: 128 d-rows x 32 n
        const int slot = vc & 1, n0 = nt * 128 + vc * 32;
#pragma unroll
        for (int r = 0; r < 4; ++r) {
            const int idx = tid + r * 128;
            const int row = idx >> 2, col = (idx & 3) * 8;
            cpa16(vpl(slot) + row * SSTR + col, Vt + (size_t)row * 2048 + n0 + col);
        }
        asm volatile("cp.async.commit_group;" ::: "memory");
    };

    issueK(0, 0);
    issueK(0, 1);

    float c[16][4] = {};   // S tile: m16 x n128 per warp
    float o[16][4] = {};   // O tile: m16 x d128 per warp (persistent)
    const int lrow = lane & 15, lkh = (lane >> 4) * 8;
    const int qrow = (warp * 16 + lrow) * ASTR;

    for (int nt = 0; nt < 16; ++nt) {
        // ---- S phase: 4 d-chunks ----
#pragma unroll
        for (int kc = 0; kc < 4; ++kc) {
            asm volatile("cp.async.wait_group 1;" ::: "memory");
            __syncthreads();
            const int slot = kc & 1;
#pragma unroll
            for (int s = 0; s < 2; ++s) {
                const int ks = s * 16;
                uint32_t a0[4], a1[4];
                ldm4(a0, Q0 + qrow + kc * 32 + ks + lkh);
                ldm4(a1, Q1 + qrow + kc * 32 + ks + lkh);
#pragma unroll
                for (int nn = 0; nn < 8; ++nn) {
                    uint32_t bh[4];
                    ldm4(bh, kpl(slot, 0) + (nn * 16 + lrow) * SSTR + ks + lkh);
                    mma16816(c[2 * nn],     a0, bh[0], bh[2]);
                    mma16816(c[2 * nn + 1], a0, bh[1], bh[3]);
                    mma16816(c[2 * nn],     a1, bh[0], bh[2]);
                    mma16816(c[2 * nn + 1], a1, bh[1], bh[3]);
                    uint32_t bl[4];
                    ldm4(bl, kpl(slot, 1) + (nn * 16 + lrow) * SSTR + ks + lkh);
                    mma16816(c[2 * nn],     a0, bl[0], bl[2]);
                    mma16816(c[2 * nn + 1], a0, bl[1], bl[3]);
                }
            }
            __syncthreads();
            if      (kc == 0) issueK(nt, 2);
            else if (kc == 1) issueK(nt, 3);
            else if (kc == 2) issueV(nt, 0);
            else              issueV(nt, 1);
        }

        // ---- PV phase: 4 n-chunks (k = keys) ----
#pragma unroll
        for (int vc = 0; vc < 4; ++vc) {
            if (nt == 15 && vc == 3) asm volatile("cp.async.wait_group 0;" ::: "memory");
            else                     asm volatile("cp.async.wait_group 1;" ::: "memory");
            __syncthreads();
            const int slot = vc & 1;
#pragma unroll
            for (int s = 0; s < 2; ++s) {
                const int j = vc * 2 + s;      // k16-step 0..7 over n-tile
                uint32_t pa[4];                 // P A-frag from C tiles 2j, 2j+1
                pa[0] = sig2(c[2 * j][0],     c[2 * j][1]);
                pa[1] = sig2(c[2 * j][2],     c[2 * j][3]);
                pa[2] = sig2(c[2 * j + 1][0], c[2 * j + 1][1]);
                pa[3] = sig2(c[2 * j + 1][2], c[2 * j + 1][3]);
#pragma unroll
                for (int nn = 0; nn < 8; ++nn) {
                    uint32_t b[4];
                    ldm4(b, vpl(slot) + (nn * 16 + lrow) * SSTR + s * 16 + lkh);
                    mma16816(o[2 * nn],     pa, b[0], b[2]);
                    mma16816(o[2 * nn + 1], pa, b[1], b[3]);
                }
            }
            __syncthreads();
            if      (vc == 0) issueV(nt, 2);
            else if (vc == 1) issueV(nt, 3);
            else if (vc == 2) { if (nt < 15) issueK(nt + 1, 0); }
            else              { if (nt < 15) issueK(nt + 1, 1); }
        }

#pragma unroll
        for (int j = 0; j < 16; ++j)
#pragma unroll
            for (int q = 0; q < 4; ++q) c[j][q] = 0.f;
    }

    // ---- epilogue: O -> g_Valshi (vals1 = colsum - O1) ----
#pragma unroll
    for (int j = 0; j < 16; ++j)
#pragma unroll
        for (int p = 0; p < 2; ++p) {
            const int m = m0 + warp * 16 + (lane >> 2) + p * 8;
            const int nl = j * 8 + (lane & 3) * 2;
            const int b = nl >> 6, d = nl & 63;
            float v0 = o[j][2 * p], v1 = o[j][2 * p + 1];
            if (b) {
                v0 = g_Colsum[h * 64 + d]     - v0;
                v1 = g_Colsum[h * 64 + d + 1] - v1;
            }
            *(__half2*)&g_Valshi[((size_t)(b * 2048 + m)) * 1024 + h * 64 + d] =
                __floats2half2_rn(v0, v1);
        }
}

// ---------------------------------------------------------------------------
// prep kernels
// ---------------------------------------------------------------------------
__global__ __launch_bounds__(256) void split_x_kernel(const float* __restrict__ x)
{
    const size_t i = ((size_t)blockIdx.x * 256 + threadIdx.x) * 4;
    float4 v = *(const float4*)(x + i);
    splitstore(&g_xhi[i],     &g_xlo[i],     v.x, v.y);
    splitstore(&g_xhi[i + 2], &g_xlo[i + 2], v.z, v.w);
}

__global__ __launch_bounds__(256) void trw_kernel(
    const float* __restrict__ w0, const float* __restrict__ w1,
    const float* __restrict__ w2, const float* __restrict__ w3)
{
    const float* W = (blockIdx.z == 0) ? w0 : (blockIdx.z == 1) ? w1
                     : (blockIdx.z == 2) ? w2 : w3;
    __shared__ float t[32][33];
    const int bx = blockIdx.x * 32, by = blockIdx.y * 32;
    const int tx = threadIdx.x & 31, ty8 = threadIdx.x >> 5;
#pragma unroll
    for (int s = 0; s < 4; ++s)
        t[ty8 + s * 8][tx] = W[(size_t)(by + ty8 + s * 8) * 1024 + bx + tx];
    __syncthreads();
    __half* Dh = g_wThi + (size_t)blockIdx.z * 1048576;
    __half* Dl = g_wTlo + (size_t)blockIdx.z * 1048576;
#pragma unroll
    for (int s = 0; s < 4; ++s) {
        const int ty = ty8 + s * 8;
        const float v = t[tx][ty];
        const size_t o = (size_t)(bx + ty) * 1024 + by + tx;
        __half h = __float2half_rn(v);
        Dh[o] = h;
        Dl[o] = __float2half_rn(v - __half2float(h));
    }
}

// transpose V per (head, 128-s-chunk) + deterministic colsum partials of V1
__global__ __launch_bounds__(256) void trv_kernel()
{
    extern __shared__ float tl[];   // [128][129]
    const int sc = blockIdx.x, h = blockIdx.y;
    const int s0 = sc * 128;
    const __half* V = g_V16 + ((size_t)h * 2048 + s0) * 128;

    for (int i = threadIdx.x; i < 128 * 128; i += 256)
        tl[(i >> 7) * 129 + (i & 127)] = __half2float(V[i]);
    __syncthreads();

    if (threadIdx.x < 64) {
        float acc = 0.f;
        for (int s = 0; s < 128; ++s) acc += tl[s * 129 + 64 + threadIdx.x];
        g_ColPart[((size_t)h * 16 + sc) * 64 + threadIdx.x] = acc;
    }

    const int dp = threadIdx.x & 127, seg = threadIdx.x >> 7;
    __half* Th = g_Vthi + ((size_t)h * 128 + dp) * 2048 + s0 + seg * 64;
#pragma unroll 8
    for (int j = 0; j < 64; ++j)
        Th[j] = __float2half_rn(tl[(seg * 64 + j) * 129 + dp]);
}

__global__ void redc_kernel()
{
    const int t = threadIdx.x;   // 1024 = 16h * 64d
    const int h = t >> 6, d = t & 63;
    float a = 0.f;
    for (int sc = 0; sc < 16; ++sc)
        a += g_ColPart[((size_t)h * 16 + sc) * 64 + d];
    g_Colsum[t] = a;
}

// ---------------------------------------------------------------------------
extern "C" void kernel_launch(void* const* d_in, const int* in_sizes, int n_in,
                              void* d_out, int out_size)
{
    const float* x  = (const float*)d_in[0];
    const float* wq = (const float*)d_in[1];
    const float* wk = (const float*)d_in[2];
    const float* wv = (const float*)d_in[3];
    const float* wo = (const float*)d_in[4];
    float* out = (float*)d_out;

    const int PB    = PLANEH * 2;                         // 10240 B / plane
    const int SM_QK = 2 * 4 * PB;                         //  81920 (3-term, 2-stage)
    const int SM_1T = 3 * 2 * PB;                         //  61440 (1-term, 3-stage)
    const int SM_FA = (2 * 64 * ASTR) * 2 + 6 * PB;       //  96256 (fused attn)
    const int SMT   = 128 * 129 * 4;                      //  66048

    cudaFuncSetAttribute(gemm_kernel<1024, 3, EPI_QK,  2, 2>, cudaFuncAttributeMaxDynamicSharedMemorySize, SM_QK);
    cudaFuncSetAttribute(gemm_kernel<1024, 1, EPI_V,   2, 3>, cudaFuncAttributeMaxDynamicSharedMemorySize, SM_1T);
    cudaFuncSetAttribute(gemm_kernel<1024, 1, EPI_OUT, 2, 3>, cudaFuncAttributeMaxDynamicSharedMemorySize, SM_1T);
    cudaFuncSetAttribute(fattn_kernel, cudaFuncAttributeMaxDynamicSharedMemorySize, SM_FA);
    cudaFuncSetAttribute(trv_kernel,   cudaFuncAttributeMaxDynamicSharedMemorySize, SMT);

    split_x_kernel<<<4096, 256>>>(x);
    trw_kernel<<<dim3(32, 32, 4), 256>>>(wq, wk, wv, wo);

    gemm_kernel<1024, 3, EPI_QK, 2, 2><<<dim3(8, 32, 2), 256, SM_QK>>>(nullptr);
    gemm_kernel<1024, 1, EPI_V,  2, 3><<<dim3(8, 32, 1), 256, SM_1T>>>(nullptr);

    trv_kernel<<<dim3(16, 16), 256, SMT>>>();
    redc_kernel<<<1, 1024>>>();

    fattn_kernel<<<dim3(32, 16), 128, SM_FA>>>();

    gemm_kernel<1024, 1, EPI_OUT, 2, 3><<<dim3(8, 32, 1), 256, SM_1T>>>(out);
}

// round 14
// speedup vs baseline: 2.1154x; 1.0358x over previous
#include <cuda_runtime.h>
#include <cuda_fp16.h>
#include <cstdint>

// ---------------------------------------------------------------------------
// B=2,S=2048,D=1024,H=16,HD=64, scale=32. softmax over batch (B=2) ==
//   P     = sigmoid((Q0K0^T - Q1K1^T)/32)   per head [2048x2048]
//   vals0 = P @ V0 ;  vals1 = colsum(V1) - P @ V1
// fp16 mma.sync m16n8k16; hi/lo split planes:
//   Q/K proj: 3-term | fused score+PV (flash, V via ldmatrix.trans) |
//   V proj, out: 1-term
// ---------------------------------------------------------------------------

__device__ __align__(128) __half g_xhi[4096 * 1024];
__device__ __align__(128) __half g_xlo[4096 * 1024];
__device__ __align__(128) __half g_wThi[4 * 1024 * 1024];   // [z][n][k]
__device__ __align__(128) __half g_wTlo[4 * 1024 * 1024];
__device__ __align__(128) __half g_Qhi[16 * 2048 * 128];    // [h][s][b*64+d]
__device__ __align__(128) __half g_Qlo[16 * 2048 * 128];
__device__ __align__(128) __half g_Khi[16 * 2048 * 128];    // K1 negated
__device__ __align__(128) __half g_Klo[16 * 2048 * 128];
__device__ __align__(128) __half g_V16[16 * 2048 * 128];    // fp16 V [h][s][b*64+d]
__device__ __align__(128) __half g_Valshi[4096 * 1024];     // [b*2048+q][h*64+d]
__device__ float g_ColPart[16 * 16 * 64];
__device__ float g_Colsum[16 * 64];

#define SSTR   40                 // halfs per smem row, 32-K chunks (+8 pad)
#define PLANEH (128 * SSTR)       // 5120 halfs / 10240 B
#define VSTR   136                // halfs per row for trans-read V chunks

// ---------------------------------------------------------------------------
static __device__ __forceinline__ void cpa16(const __half* dst_smem, const void* src) {
    uint32_t d = (uint32_t)__cvta_generic_to_shared(dst_smem);
    asm volatile("cp.async.cg.shared.global [%0], [%1], 16;" :: "r"(d), "l"(src));
}
static __device__ __forceinline__ void ldm4(uint32_t r[4], const void* p) {
    uint32_t a = (uint32_t)__cvta_generic_to_shared(p);
    asm volatile("ldmatrix.sync.aligned.m8n8.x4.shared.b16 {%0,%1,%2,%3}, [%4];"
                 : "=r"(r[0]), "=r"(r[1]), "=r"(r[2]), "=r"(r[3]) : "r"(a));
}
static __device__ __forceinline__ void ldm4t(uint32_t r[4], const void* p) {
    uint32_t a = (uint32_t)__cvta_generic_to_shared(p);
    asm volatile("ldmatrix.sync.aligned.m8n8.x4.trans.shared.b16 {%0,%1,%2,%3}, [%4];"
                 : "=r"(r[0]), "=r"(r[1]), "=r"(r[2]), "=r"(r[3]) : "r"(a));
}
static __device__ __forceinline__ void mma16816(float c[4], const uint32_t a[4],
                                                uint32_t b0, uint32_t b1) {
    asm volatile(
        "mma.sync.aligned.m16n8k16.row.col.f32.f16.f16.f32 "
        "{%0,%1,%2,%3}, {%4,%5,%6,%7}, {%8,%9}, {%0,%1,%2,%3};"
        : "+f"(c[0]), "+f"(c[1]), "+f"(c[2]), "+f"(c[3])
        : "r"(a[0]), "r"(a[1]), "r"(a[2]), "r"(a[3]), "r"(b0), "r"(b1));
}
static __device__ __forceinline__ void splitstore(__half* hp, __half* lp,
                                                  float v0, float v1) {
    __half h0 = __float2half_rn(v0), h1 = __float2half_rn(v1);
    *(__half2*)hp = __halves2half2(h0, h1);
    *(__half2*)lp = __halves2half2(__float2half_rn(v0 - __half2float(h0)),
                                   __float2half_rn(v1 - __half2float(h1)));
}
// sigmoid(S/32) pair -> packed fp16x2 (lo = first value)
static __device__ __forceinline__ uint32_t sig2(float f0, float f1) {
    const float NK = -0.04508422f;   // -log2(e)/32
    __half2 m2 = __floats2half2_rn(f0 * NK, f1 * NK);
    __half2 P2 = h2rcp(__hadd2(__float2half2_rn(1.0f), h2exp2(m2)));
    return *reinterpret_cast<uint32_t*>(&P2);
}

enum { EPI_QK = 0, EPI_V, EPI_OUT };

// ---------------------------------------------------------------------------
// 128x128 NT GEMM, fp16 mma + ldmatrix, NSTG-stage cp.async, fused epilogue.
// NTERM=3: Ahi*Bhi + Alo*Bhi + Ahi*Blo ; NTERM=1: A*Bhi
// ---------------------------------------------------------------------------
template <int KTOT, int NTERM, int EPI, int OCC, int NSTG>
__global__ __launch_bounds__(256, OCC) void gemm_kernel(float* outp)
{
    extern __shared__ __align__(128) __half sm[];
    const int NA = (NTERM == 3) ? 2 : 1;
    const int NB = (NTERM >= 2) ? 2 : 1;
    const int NT = NA + NB;

    const int tid = threadIdx.x, warp = tid >> 5, lane = tid & 31;
    const int wm = (warp & 3) * 32, wn = (warp >> 2) * 64;
    const int m0 = blockIdx.y * 128, n0 = blockIdx.x * 128, z = blockIdx.z;

    const __half *Ahi, *Alo = nullptr, *Bhi, *Blo = nullptr;
    int lda, ldb;
    if (EPI == EPI_QK) {
        Ahi = g_xhi; Alo = g_xlo; lda = 1024;
        Bhi = g_wThi + (size_t)z * 1048576; Blo = g_wTlo + (size_t)z * 1048576; ldb = 1024;
    } else if (EPI == EPI_V) {
        Ahi = g_xhi; lda = 1024;
        Bhi = g_wThi + (size_t)2 * 1048576; ldb = 1024;
    } else {
        Ahi = g_Valshi; lda = 1024;
        Bhi = g_wThi + (size_t)3 * 1048576; ldb = 1024;
    }

    auto plane = [&](int st, int pl) -> __half* { return sm + (st * NT + pl) * PLANEH; };

    auto load_stage = [&](int ch) {
        const int st = ch % NSTG, k0 = ch * 32;
#pragma unroll
        for (int r = 0; r < 2; ++r) {
            const int idx = tid + r * 256;
            const int row = idx >> 2, col = (idx & 3) * 8;
            cpa16(plane(st, 0) + row * SSTR + col, Ahi + (size_t)(m0 + row) * lda + k0 + col);
            if (NA == 2)
                cpa16(plane(st, 1) + row * SSTR + col, Alo + (size_t)(m0 + row) * lda + k0 + col);
            cpa16(plane(st, NA) + row * SSTR + col, Bhi + (size_t)(n0 + row) * ldb + k0 + col);
            if (NB == 2)
                cpa16(plane(st, NA + 1) + row * SSTR + col, Blo + (size_t)(n0 + row) * ldb + k0 + col);
        }
        asm volatile("cp.async.commit_group;" ::: "memory");
    };

    float c[2][8][4] = {};
    const int nCh = KTOT / 32;
    load_stage(0);
    if (NSTG == 3 && nCh > 1) load_stage(1);

    const int lrow = lane & 15, lkh = (lane >> 4) * 8;

    for (int ch = 0; ch < nCh; ++ch) {
        if (NSTG == 3) {
            if (ch + 1 < nCh) asm volatile("cp.async.wait_group 1;" ::: "memory");
            else              asm volatile("cp.async.wait_group 0;" ::: "memory");
            __syncthreads();
            if (ch + 2 < nCh) load_stage(ch + 2);
        } else {
            if (ch + 1 < nCh) {
                __syncthreads();
                load_stage(ch + 1);
                asm volatile("cp.async.wait_group 1;" ::: "memory");
            } else {
                asm volatile("cp.async.wait_group 0;" ::: "memory");
            }
            __syncthreads();
        }
        const int buf = ch % NSTG;

#pragma unroll
        for (int s = 0; s < 2; ++s) {
            const int ks = s * 16;
            uint32_t a[2][2][4];
#pragma unroll
            for (int pa = 0; pa < NA; ++pa)
#pragma unroll
                for (int mt = 0; mt < 2; ++mt)
                    ldm4(a[pa][mt], plane(buf, pa) + (wm + mt * 16 + lrow) * SSTR + ks + lkh);

            uint32_t bh[4][4];
#pragma unroll
            for (int np = 0; np < 4; ++np) {
                ldm4(bh[np], plane(buf, NA) + (wn + np * 16 + lrow) * SSTR + ks + lkh);
#pragma unroll
                for (int mt = 0; mt < 2; ++mt) {
                    mma16816(c[mt][2 * np],     a[0][mt], bh[np][0], bh[np][2]);
                    mma16816(c[mt][2 * np + 1], a[0][mt], bh[np][1], bh[np][3]);
                }
            }
            if (NA == 2) {
#pragma unroll
                for (int np = 0; np < 4; ++np)
#pragma unroll
                    for (int mt = 0; mt < 2; ++mt) {
                        mma16816(c[mt][2 * np],     a[1][mt], bh[np][0], bh[np][2]);
                        mma16816(c[mt][2 * np + 1], a[1][mt], bh[np][1], bh[np][3]);
                    }
            }
            if (NB == 2) {
#pragma unroll
                for (int np = 0; np < 4; ++np) {
                    uint32_t bl[4];
                    ldm4(bl, plane(buf, NA + 1) + (wn + np * 16 + lrow) * SSTR + ks + lkh);
#pragma unroll
                    for (int mt = 0; mt < 2; ++mt) {
                        mma16816(c[mt][2 * np],     a[0][mt], bl[0], bl[2]);
                        mma16816(c[mt][2 * np + 1], a[0][mt], bl[1], bl[3]);
                    }
                }
            }
        }
    }

    // ---- epilogue: m = m0+wm+mt*16+lane/4+p*8 ; n = n0+wn+nt*8+(lane%4)*2 ----
#pragma unroll
    for (int mt = 0; mt < 2; ++mt)
#pragma unroll
        for (int nt = 0; nt < 8; ++nt)
#pragma unroll
            for (int p = 0; p < 2; ++p) {
                const int m = m0 + wm + mt * 16 + (lane >> 2) + p * 8;
                const int nl = wn + nt * 8 + (lane & 3) * 2;
                float v0 = c[mt][nt][2 * p], v1 = c[mt][nt][2 * p + 1];

                if (EPI == EPI_QK) {
                    const int b = m >> 11, s = m & 2047;
                    const int n = n0 + nl, h = n >> 6, d = n & 63;
                    const size_t base = ((size_t)(h * 2048 + s)) * 128 + b * 64 + d;
                    if (z == 1 && b == 1) { v0 = -v0; v1 = -v1; }
                    __half* Dh = (z == 0) ? g_Qhi : g_Khi;
                    __half* Dl = (z == 0) ? g_Qlo : g_Klo;
                    splitstore(&Dh[base], &Dl[base], v0, v1);
                } else if (EPI == EPI_V) {
                    const int b = m >> 11, s = m & 2047;
                    const int n = n0 + nl, h = n >> 6, d = n & 63;
                    *(__half2*)&g_V16[((size_t)(h * 2048 + s)) * 128 + b * 64 + d] =
                        __floats2half2_rn(v0, v1);
                } else {
                    *(float2*)&outp[(size_t)m * 1024 + n0 + nl] = make_float2(v0, v1);
                }
            }
}

// ---------------------------------------------------------------------------
// Fused score+PV (flash style). Per CTA: 64 q-rows of one head.
// Loop over 16 n-tiles (128 keys): S = 3-term QK^T (Q hi/lo resident,
// kc-split 32-col planes), P = sigmoid(S/32) -> fp16 A-frags in regs,
// O += P @ V^T with V read straight from g_V16 via ldmatrix.trans.
// 128 threads = 4 warps, warp = 16 m-rows. smem 99328 B -> occ 2.
// ---------------------------------------------------------------------------
__global__ __launch_bounds__(128, 2) void fattn_kernel()
{
    extern __shared__ __align__(128) __half sm[];
    // Q: [2 planes][4 kc][64 x 40]  (20480 halfs)
    auto qpl = [&](int p, int kc) -> __half* { return sm + (p * 4 + kc) * 2560; };
    // K: [2 slots][2 planes][128 x 40] (20480 halfs)
    auto kpl = [&](int slot, int pl) -> __half* { return sm + 20480 + (slot * 2 + pl) * PLANEH; };
    // V: [2 slots][32 x 136] (8704 halfs)
    auto vpl = [&](int slot) -> __half* { return sm + 40960 + slot * (32 * VSTR); };

    const int tid = threadIdx.x, warp = tid >> 5, lane = tid & 31;
    const int h = blockIdx.y, m0 = blockIdx.x * 64;

    const __half* Qh = g_Qhi + ((size_t)h * 2048 + m0) * 128;
    const __half* Ql = g_Qlo + ((size_t)h * 2048 + m0) * 128;
    const __half* Kh = g_Khi + (size_t)h * 2048 * 128;
    const __half* Kl = g_Klo + (size_t)h * 2048 * 128;
    const __half* Vs = g_V16 + (size_t)h * 2048 * 128;   // [s][128]

    // group 0: resident Q (both planes, kc-split)
#pragma unroll
    for (int r = 0; r < 8; ++r) {
        const int idx = tid + r * 128;
        const int row = idx >> 4, col = (idx & 15) * 8;
        const int kc = col >> 5, cc = col & 31;
        cpa16(qpl(0, kc) + row * SSTR + cc, Qh + row * 128 + col);
        cpa16(qpl(1, kc) + row * SSTR + cc, Ql + row * 128 + col);
    }
    asm volatile("cp.async.commit_group;" ::: "memory");

    auto issueK = [&](int nt, int kc) {   // K chunk: 128 n-rows x 32 d (hi+lo)
        const int slot = kc & 1, k0 = kc * 32;
#pragma unroll
        for (int r = 0; r < 4; ++r) {
            const int idx = tid + r * 128;
            const int row = idx >> 2, col = (idx & 3) * 8;
            const size_t src = (size_t)(nt * 128 + row) * 128 + k0 + col;
            cpa16(kpl(slot, 0) + row * SSTR + col, Kh + src);
            cpa16(kpl(slot, 1) + row * SSTR + col, Kl + src);
        }
        asm volatile("cp.async.commit_group;" ::: "memory");
    };
    auto issueV = [&](int nt, int vc) {   // V s-chunk: 32 key-rows x 128 d
        const int slot = vc & 1;
#pragma unroll
        for (int r = 0; r < 4; ++r) {
            const int idx = tid + r * 128;
            const int row = idx >> 4, col = (idx & 15) * 8;
            cpa16(vpl(slot) + row * VSTR + col,
                  Vs + (size_t)(nt * 128 + vc * 32 + row) * 128 + col);
        }
        asm volatile("cp.async.commit_group;" ::: "memory");
    };

    issueK(0, 0);
    issueK(0, 1);

    float c[16][4] = {};   // S tile: m16 x n128 per warp
    float o[16][4] = {};   // O tile: m16 x d128 per warp (persistent)
    const int lrow = lane & 15, lkh = (lane >> 4) * 8;
    const int qrow = (warp * 16 + lrow) * SSTR;

    for (int nt = 0; nt < 16; ++nt) {
        // ---- S phase: 4 d-chunks ----
#pragma unroll
        for (int kc = 0; kc < 4; ++kc) {
            asm volatile("cp.async.wait_group 1;" ::: "memory");
            __syncthreads();
            const int slot = kc & 1;
#pragma unroll
            for (int s = 0; s < 2; ++s) {
                const int ks = s * 16;
                uint32_t a0[4], a1[4];
                ldm4(a0, qpl(0, kc) + qrow + ks + lkh);
                ldm4(a1, qpl(1, kc) + qrow + ks + lkh);
#pragma unroll
                for (int nn = 0; nn < 8; ++nn) {
                    uint32_t bh[4];
                    ldm4(bh, kpl(slot, 0) + (nn * 16 + lrow) * SSTR + ks + lkh);
                    mma16816(c[2 * nn],     a0, bh[0], bh[2]);
                    mma16816(c[2 * nn + 1], a0, bh[1], bh[3]);
                    mma16816(c[2 * nn],     a1, bh[0], bh[2]);
                    mma16816(c[2 * nn + 1], a1, bh[1], bh[3]);
                    uint32_t bl[4];
                    ldm4(bl, kpl(slot, 1) + (nn * 16 + lrow) * SSTR + ks + lkh);
                    mma16816(c[2 * nn],     a0, bl[0], bl[2]);
                    mma16816(c[2 * nn + 1], a0, bl[1], bl[3]);
                }
            }
            __syncthreads();
            if      (kc == 0) issueK(nt, 2);
            else if (kc == 1) issueK(nt, 3);
            else if (kc == 2) issueV(nt, 0);
            else              issueV(nt, 1);
        }

        // ---- PV phase: 4 s-chunks of 32 keys ----
#pragma unroll
        for (int vc = 0; vc < 4; ++vc) {
            if (nt == 15 && vc == 3) asm volatile("cp.async.wait_group 0;" ::: "memory");
            else                     asm volatile("cp.async.wait_group 1;" ::: "memory");
            __syncthreads();
            const int slot = vc & 1;
#pragma unroll
            for (int s = 0; s < 2; ++s) {
                const int j = vc * 2 + s;      // k16-step 0..7 over n-tile
                uint32_t pa[4];                 // P A-frag from C tiles 2j, 2j+1
                pa[0] = sig2(c[2 * j][0],     c[2 * j][1]);
                pa[1] = sig2(c[2 * j][2],     c[2 * j][3]);
                pa[2] = sig2(c[2 * j + 1][0], c[2 * j + 1][1]);
                pa[3] = sig2(c[2 * j + 1][2], c[2 * j + 1][3]);
#pragma unroll
                for (int nn = 0; nn < 8; ++nn) {
                    uint32_t b[4];
                    ldm4t(b, vpl(slot) + (s * 16 + lrow) * VSTR + nn * 16 + lkh);
                    mma16816(o[2 * nn],     pa, b[0], b[1]);
                    mma16816(o[2 * nn + 1], pa, b[2], b[3]);
                }
            }
            __syncthreads();
            if      (vc == 0) issueV(nt, 2);
            else if (vc == 1) issueV(nt, 3);
            else if (vc == 2) { if (nt < 15) issueK(nt + 1, 0); }
            else              { if (nt < 15) issueK(nt + 1, 1); }
        }

#pragma unroll
        for (int j = 0; j < 16; ++j)
#pragma unroll
            for (int q = 0; q < 4; ++q) c[j][q] = 0.f;
    }

    // ---- epilogue: O -> g_Valshi (vals1 = colsum - O1) ----
#pragma unroll
    for (int j = 0; j < 16; ++j)
#pragma unroll
        for (int p = 0; p < 2; ++p) {
            const int m = m0 + warp * 16 + (lane >> 2) + p * 8;
            const int nl = j * 8 + (lane & 3) * 2;
            const int b = nl >> 6, d = nl & 63;
            float v0 = o[j][2 * p], v1 = o[j][2 * p + 1];
            if (b) {
                v0 = g_Colsum[h * 64 + d]     - v0;
                v1 = g_Colsum[h * 64 + d + 1] - v1;
            }
            *(__half2*)&g_Valshi[((size_t)(b * 2048 + m)) * 1024 + h * 64 + d] =
                __floats2half2_rn(v0, v1);
        }
}

// ---------------------------------------------------------------------------
// prep kernels
// ---------------------------------------------------------------------------
__global__ __launch_bounds__(256) void split_x_kernel(const float* __restrict__ x)
{
    const size_t i = ((size_t)blockIdx.x * 256 + threadIdx.x) * 4;
    float4 v = *(const float4*)(x + i);
    splitstore(&g_xhi[i],     &g_xlo[i],     v.x, v.y);
    splitstore(&g_xhi[i + 2], &g_xlo[i + 2], v.z, v.w);
}

__global__ __launch_bounds__(256) void trw_kernel(
    const float* __restrict__ w0, const float* __restrict__ w1,
    const float* __restrict__ w2, const float* __restrict__ w3)
{
    const float* W = (blockIdx.z == 0) ? w0 : (blockIdx.z == 1) ? w1
                     : (blockIdx.z == 2) ? w2 : w3;
    __shared__ float t[32][33];
    const int bx = blockIdx.x * 32, by = blockIdx.y * 32;
    const int tx = threadIdx.x & 31, ty8 = threadIdx.x >> 5;
#pragma unroll
    for (int s = 0; s < 4; ++s)
        t[ty8 + s * 8][tx] = W[(size_t)(by + ty8 + s * 8) * 1024 + bx + tx];
    __syncthreads();
    __half* Dh = g_wThi + (size_t)blockIdx.z * 1048576;
    __half* Dl = g_wTlo + (size_t)blockIdx.z * 1048576;
#pragma unroll
    for (int s = 0; s < 4; ++s) {
        const int ty = ty8 + s * 8;
        const float v = t[tx][ty];
        const size_t o = (size_t)(bx + ty) * 1024 + by + tx;
        __half h = __float2half_rn(v);
        Dh[o] = h;
        Dl[o] = __float2half_rn(v - __half2float(h));
    }
}

// colsum partials of V1 straight from g_V16 (coalesced 128B rows)
__global__ void colpart_kernel()
{
    const int sc = blockIdx.x, h = blockIdx.y, d = threadIdx.x;  // 64 threads
    const __half* v = g_V16 + ((size_t)(h * 2048 + sc * 128)) * 128 + 64 + d;
    float s = 0.f;
    for (int i = 0; i < 128; ++i) s += __half2float(v[(size_t)i * 128]);
    g_ColPart[((size_t)h * 16 + sc) * 64 + d] = s;
}

__global__ void redc_kernel()
{
    const int t = threadIdx.x;   // 1024 = 16h * 64d
    const int h = t >> 6, d = t & 63;
    float a = 0.f;
    for (int sc = 0; sc < 16; ++sc)
        a += g_ColPart[((size_t)h * 16 + sc) * 64 + d];
    g_Colsum[t] = a;
}

// ---------------------------------------------------------------------------
extern "C" void kernel_launch(void* const* d_in, const int* in_sizes, int n_in,
                              void* d_out, int out_size)
{
    const float* x  = (const float*)d_in[0];
    const float* wq = (const float*)d_in[1];
    const float* wk = (const float*)d_in[2];
    const float* wv = (const float*)d_in[3];
    const float* wo = (const float*)d_in[4];
    float* out = (float*)d_out;

    const int PB    = PLANEH * 2;                         // 10240 B / plane
    const int SM_QK = 2 * 4 * PB;                         //  81920 (3-term, 2-stage)
    const int SM_1T = 3 * 2 * PB;                         //  61440 (1-term, 3-stage)
    const int SM_FA = (20480 + 20480 + 8704) * 2;         //  99328 (fused attn)

    cudaFuncSetAttribute(gemm_kernel<1024, 3, EPI_QK,  2, 2>, cudaFuncAttributeMaxDynamicSharedMemorySize, SM_QK);
    cudaFuncSetAttribute(gemm_kernel<1024, 1, EPI_V,   2, 3>, cudaFuncAttributeMaxDynamicSharedMemorySize, SM_1T);
    cudaFuncSetAttribute(gemm_kernel<1024, 1, EPI_OUT, 2, 3>, cudaFuncAttributeMaxDynamicSharedMemorySize, SM_1T);
    cudaFuncSetAttribute(fattn_kernel, cudaFuncAttributeMaxDynamicSharedMemorySize, SM_FA);

    split_x_kernel<<<4096, 256>>>(x);
    trw_kernel<<<dim3(32, 32, 4), 256>>>(wq, wk, wv, wo);

    gemm_kernel<1024, 3, EPI_QK, 2, 2><<<dim3(8, 32, 2), 256, SM_QK>>>(nullptr);
    gemm_kernel<1024, 1, EPI_V,  2, 3><<<dim3(8, 32, 1), 256, SM_1T>>>(nullptr);

    colpart_kernel<<<dim3(16, 16), 64>>>();
    redc_kernel<<<1, 1024>>>();

    fattn_kernel<<<dim3(32, 16), 128, SM_FA>>>();

    gemm_kernel<1024, 1, EPI_OUT, 2, 3><<<dim3(8, 32, 1), 256, SM_1T>>>(out);
}

// round 15
// speedup vs baseline: 2.1504x; 1.0165x over previous
#include <cuda_runtime.h>
#include <cuda_fp16.h>
#include <cstdint>

// ---------------------------------------------------------------------------
// B=2,S=2048,D=1024,H=16,HD=64, scale=32. softmax over batch (B=2) ==
//   P     = sigmoid((Q0K0^T - Q1K1^T)/32)   per head [2048x2048]
//   vals0 = P @ V0 ;  vals1 = colsum(V1) - P @ V1
// fp16 mma.sync m16n8k16; hi/lo split planes:
//   Q/K proj: 3-term | fused score+PV (flash, V via ldmatrix.trans) |
//   V proj (+fused colsum partials), out: 1-term
// ---------------------------------------------------------------------------

__device__ __align__(128) __half g_xhi[4096 * 1024];
__device__ __align__(128) __half g_xlo[4096 * 1024];
__device__ __align__(128) __half g_wThi[4 * 1024 * 1024];   // [z][n][k]
__device__ __align__(128) __half g_wTlo[4 * 1024 * 1024];
__device__ __align__(128) __half g_Qhi[16 * 2048 * 128];    // [h][s][b*64+d]
__device__ __align__(128) __half g_Qlo[16 * 2048 * 128];
__device__ __align__(128) __half g_Khi[16 * 2048 * 128];    // K1 negated
__device__ __align__(128) __half g_Klo[16 * 2048 * 128];
__device__ __align__(128) __half g_V16[16 * 2048 * 128];    // fp16 V [h][s][b*64+d]
__device__ __align__(128) __half g_Valshi[4096 * 1024];     // [b*2048+q][h*64+d]
__device__ float g_ColPart[16 * 16 * 64];                   // [h][sc][d]

#define SSTR   40                 // halfs per smem row, 32-K chunks (+8 pad)
#define PLANEH (128 * SSTR)       // 5120 halfs / 10240 B
#define VSTR   136                // halfs per row for trans-read V chunks

// ---------------------------------------------------------------------------
static __device__ __forceinline__ void cpa16(const __half* dst_smem, const void* src) {
    uint32_t d = (uint32_t)__cvta_generic_to_shared(dst_smem);
    asm volatile("cp.async.cg.shared.global [%0], [%1], 16;" :: "r"(d), "l"(src));
}
static __device__ __forceinline__ void ldm4(uint32_t r[4], const void* p) {
    uint32_t a = (uint32_t)__cvta_generic_to_shared(p);
    asm volatile("ldmatrix.sync.aligned.m8n8.x4.shared.b16 {%0,%1,%2,%3}, [%4];"
                 : "=r"(r[0]), "=r"(r[1]), "=r"(r[2]), "=r"(r[3]) : "r"(a));
}
static __device__ __forceinline__ void ldm4t(uint32_t r[4], const void* p) {
    uint32_t a = (uint32_t)__cvta_generic_to_shared(p);
    asm volatile("ldmatrix.sync.aligned.m8n8.x4.trans.shared.b16 {%0,%1,%2,%3}, [%4];"
                 : "=r"(r[0]), "=r"(r[1]), "=r"(r[2]), "=r"(r[3]) : "r"(a));
}
static __device__ __forceinline__ void mma16816(float c[4], const uint32_t a[4],
                                                uint32_t b0, uint32_t b1) {
    asm volatile(
        "mma.sync.aligned.m16n8k16.row.col.f32.f16.f16.f32 "
        "{%0,%1,%2,%3}, {%4,%5,%6,%7}, {%8,%9}, {%0,%1,%2,%3};"
        : "+f"(c[0]), "+f"(c[1]), "+f"(c[2]), "+f"(c[3])
        : "r"(a[0]), "r"(a[1]), "r"(a[2]), "r"(a[3]), "r"(b0), "r"(b1));
}
static __device__ __forceinline__ void splitstore(__half* hp, __half* lp,
                                                  float v0, float v1) {
    __half h0 = __float2half_rn(v0), h1 = __float2half_rn(v1);
    *(__half2*)hp = __halves2half2(h0, h1);
    *(__half2*)lp = __halves2half2(__float2half_rn(v0 - __half2float(h0)),
                                   __float2half_rn(v1 - __half2float(h1)));
}
// sigmoid(S/32) pair -> packed fp16x2 (lo = first value)
static __device__ __forceinline__ uint32_t sig2(float f0, float f1) {
    const float NK = -0.04508422f;   // -log2(e)/32
    __half2 m2 = __floats2half2_rn(f0 * NK, f1 * NK);
    __half2 P2 = h2rcp(__hadd2(__float2half2_rn(1.0f), h2exp2(m2)));
    return *reinterpret_cast<uint32_t*>(&P2);
}

enum { EPI_QK = 0, EPI_V, EPI_OUT };

// ---------------------------------------------------------------------------
// 128x128 NT GEMM, fp16 mma + ldmatrix, NSTG-stage cp.async, fused epilogue.
// NTERM=3: Ahi*Bhi + Alo*Bhi + Ahi*Blo ; NTERM=1: A*Bhi
// EPI_V additionally emits deterministic colsum partials of batch-1 V rows.
// ---------------------------------------------------------------------------
template <int KTOT, int NTERM, int EPI, int OCC, int NSTG>
__global__ __launch_bounds__(256, OCC) void gemm_kernel(float* outp)
{
    extern __shared__ __align__(128) __half sm[];
    const int NA = (NTERM == 3) ? 2 : 1;
    const int NB = (NTERM >= 2) ? 2 : 1;
    const int NT = NA + NB;

    const int tid = threadIdx.x, warp = tid >> 5, lane = tid & 31;
    const int wm = (warp & 3) * 32, wn = (warp >> 2) * 64;
    const int m0 = blockIdx.y * 128, n0 = blockIdx.x * 128, z = blockIdx.z;

    const __half *Ahi, *Alo = nullptr, *Bhi, *Blo = nullptr;
    int lda, ldb;
    if (EPI == EPI_QK) {
        Ahi = g_xhi; Alo = g_xlo; lda = 1024;
        Bhi = g_wThi + (size_t)z * 1048576; Blo = g_wTlo + (size_t)z * 1048576; ldb = 1024;
    } else if (EPI == EPI_V) {
        Ahi = g_xhi; lda = 1024;
        Bhi = g_wThi + (size_t)2 * 1048576; ldb = 1024;
    } else {
        Ahi = g_Valshi; lda = 1024;
        Bhi = g_wThi + (size_t)3 * 1048576; ldb = 1024;
    }

    auto plane = [&](int st, int pl) -> __half* { return sm + (st * NT + pl) * PLANEH; };

    auto load_stage = [&](int ch) {
        const int st = ch % NSTG, k0 = ch * 32;
#pragma unroll
        for (int r = 0; r < 2; ++r) {
            const int idx = tid + r * 256;
            const int row = idx >> 2, col = (idx & 3) * 8;
            cpa16(plane(st, 0) + row * SSTR + col, Ahi + (size_t)(m0 + row) * lda + k0 + col);
            if (NA == 2)
                cpa16(plane(st, 1) + row * SSTR + col, Alo + (size_t)(m0 + row) * lda + k0 + col);
            cpa16(plane(st, NA) + row * SSTR + col, Bhi + (size_t)(n0 + row) * ldb + k0 + col);
            if (NB == 2)
                cpa16(plane(st, NA + 1) + row * SSTR + col, Blo + (size_t)(n0 + row) * ldb + k0 + col);
        }
        asm volatile("cp.async.commit_group;" ::: "memory");
    };

    float c[2][8][4] = {};
    const int nCh = KTOT / 32;
    load_stage(0);
    if (NSTG == 3 && nCh > 1) load_stage(1);

    const int lrow = lane & 15, lkh = (lane >> 4) * 8;

    for (int ch = 0; ch < nCh; ++ch) {
        if (NSTG == 3) {
            if (ch + 1 < nCh) asm volatile("cp.async.wait_group 1;" ::: "memory");
            else              asm volatile("cp.async.wait_group 0;" ::: "memory");
            __syncthreads();
            if (ch + 2 < nCh) load_stage(ch + 2);
        } else {
            if (ch + 1 < nCh) {
                __syncthreads();
                load_stage(ch + 1);
                asm volatile("cp.async.wait_group 1;" ::: "memory");
            } else {
                asm volatile("cp.async.wait_group 0;" ::: "memory");
            }
            __syncthreads();
        }
        const int buf = ch % NSTG;

#pragma unroll
        for (int s = 0; s < 2; ++s) {
            const int ks = s * 16;
            uint32_t a[2][2][4];
#pragma unroll
            for (int pa = 0; pa < NA; ++pa)
#pragma unroll
                for (int mt = 0; mt < 2; ++mt)
                    ldm4(a[pa][mt], plane(buf, pa) + (wm + mt * 16 + lrow) * SSTR + ks + lkh);

            uint32_t bh[4][4];
#pragma unroll
            for (int np = 0; np < 4; ++np) {
                ldm4(bh[np], plane(buf, NA) + (wn + np * 16 + lrow) * SSTR + ks + lkh);
#pragma unroll
                for (int mt = 0; mt < 2; ++mt) {
                    mma16816(c[mt][2 * np],     a[0][mt], bh[np][0], bh[np][2]);
                    mma16816(c[mt][2 * np + 1], a[0][mt], bh[np][1], bh[np][3]);
                }
            }
            if (NA == 2) {
#pragma unroll
                for (int np = 0; np < 4; ++np)
#pragma unroll
                    for (int mt = 0; mt < 2; ++mt) {
                        mma16816(c[mt][2 * np],     a[1][mt], bh[np][0], bh[np][2]);
                        mma16816(c[mt][2 * np + 1], a[1][mt], bh[np][1], bh[np][3]);
                    }
            }
            if (NB == 2) {
#pragma unroll
                for (int np = 0; np < 4; ++np) {
                    uint32_t bl[4];
                    ldm4(bl, plane(buf, NA + 1) + (wn + np * 16 + lrow) * SSTR + ks + lkh);
#pragma unroll
                    for (int mt = 0; mt < 2; ++mt) {
                        mma16816(c[mt][2 * np],     a[0][mt], bl[0], bl[2]);
                        mma16816(c[mt][2 * np + 1], a[0][mt], bl[1], bl[3]);
                    }
                }
            }
        }
    }

    // ---- epilogue: m = m0+wm+mt*16+lane/4+p*8 ; n = n0+wn+nt*8+(lane%4)*2 ----
    float lc[8][2];
    if (EPI == EPI_V)
#pragma unroll
        for (int nt = 0; nt < 8; ++nt) { lc[nt][0] = 0.f; lc[nt][1] = 0.f; }

#pragma unroll
    for (int mt = 0; mt < 2; ++mt)
#pragma unroll
        for (int nt = 0; nt < 8; ++nt)
#pragma unroll
            for (int p = 0; p < 2; ++p) {
                const int m = m0 + wm + mt * 16 + (lane >> 2) + p * 8;
                const int nl = wn + nt * 8 + (lane & 3) * 2;
                float v0 = c[mt][nt][2 * p], v1 = c[mt][nt][2 * p + 1];

                if (EPI == EPI_QK) {
                    const int b = m >> 11, s = m & 2047;
                    const int n = n0 + nl, h = n >> 6, d = n & 63;
                    const size_t base = ((size_t)(h * 2048 + s)) * 128 + b * 64 + d;
                    if (z == 1 && b == 1) { v0 = -v0; v1 = -v1; }
                    __half* Dh = (z == 0) ? g_Qhi : g_Khi;
                    __half* Dl = (z == 0) ? g_Qlo : g_Klo;
                    splitstore(&Dh[base], &Dl[base], v0, v1);
                } else if (EPI == EPI_V) {
                    const int b = m >> 11, s = m & 2047;
                    const int n = n0 + nl, h = n >> 6, d = n & 63;
                    __half2 hv = __floats2half2_rn(v0, v1);
                    *(__half2*)&g_V16[((size_t)(h * 2048 + s)) * 128 + b * 64 + d] = hv;
                    lc[nt][0] += __half2float(__low2half(hv));
                    lc[nt][1] += __half2float(__high2half(hv));
                } else {
                    *(float2*)&outp[(size_t)m * 1024 + n0 + nl] = make_float2(v0, v1);
                }
            }

    // ---- fused colsum partials (batch-1 CTAs only; deterministic order) ----
    if (EPI == EPI_V) {
        float* colbuf = (float*)sm;   // [8 warps][128 cols]
        __syncthreads();
        if (blockIdx.y >= 16) {
#pragma unroll
            for (int nt = 0; nt < 8; ++nt)
#pragma unroll
                for (int j = 0; j < 2; ++j) {
                    float s = lc[nt][j];
                    s += __shfl_xor_sync(0xffffffffu, s, 4);
                    s += __shfl_xor_sync(0xffffffffu, s, 8);
                    s += __shfl_xor_sync(0xffffffffu, s, 16);
                    if ((lane >> 2) == 0)
                        colbuf[warp * 128 + wn + nt * 8 + (lane & 3) * 2 + j] = s;
                }
        }
        __syncthreads();
        if (blockIdx.y >= 16 && tid < 128) {
            const int col = tid, g = col >> 6;
            float s = colbuf[(g * 4 + 0) * 128 + col] + colbuf[(g * 4 + 1) * 128 + col]
                    + colbuf[(g * 4 + 2) * 128 + col] + colbuf[(g * 4 + 3) * 128 + col];
            const int n = n0 + col, h = n >> 6, d = n & 63;
            g_ColPart[((size_t)h * 16 + (blockIdx.y - 16)) * 64 + d] = s;
        }
    }
}

// ---------------------------------------------------------------------------
// Fused score+PV (flash style). Per CTA: 64 q-rows of one head.
// Colsum for this head reduced from partials in the prologue (smem csum).
// 128 threads = 4 warps, warp = 16 m-rows. smem 99584 B -> occ 2.
// ---------------------------------------------------------------------------
__global__ __launch_bounds__(128, 2) void fattn_kernel()
{
    extern __shared__ __align__(128) __half sm[];
    // Q: [2 planes][4 kc][64 x 40]  (20480 halfs)
    auto qpl = [&](int p, int kc) -> __half* { return sm + (p * 4 + kc) * 2560; };
    // K: [2 slots][2 planes][128 x 40] (20480 halfs)
    auto kpl = [&](int slot, int pl) -> __half* { return sm + 20480 + (slot * 2 + pl) * PLANEH; };
    // V: [2 slots][32 x 136] (8704 halfs)
    auto vpl = [&](int slot) -> __half* { return sm + 40960 + slot * (32 * VSTR); };
    float* csum = (float*)(sm + 49664);   // [64]

    const int tid = threadIdx.x, warp = tid >> 5, lane = tid & 31;
    const int h = blockIdx.y, m0 = blockIdx.x * 64;

    const __half* Qh = g_Qhi + ((size_t)h * 2048 + m0) * 128;
    const __half* Ql = g_Qlo + ((size_t)h * 2048 + m0) * 128;
    const __half* Kh = g_Khi + (size_t)h * 2048 * 128;
    const __half* Kl = g_Klo + (size_t)h * 2048 * 128;
    const __half* Vs = g_V16 + (size_t)h * 2048 * 128;   // [s][128]

    // group 0: resident Q (both planes, kc-split)
#pragma unroll
    for (int r = 0; r < 8; ++r) {
        const int idx = tid + r * 128;
        const int row = idx >> 4, col = (idx & 15) * 8;
        const int kc = col >> 5, cc = col & 31;
        cpa16(qpl(0, kc) + row * SSTR + cc, Qh + row * 128 + col);
        cpa16(qpl(1, kc) + row * SSTR + cc, Ql + row * 128 + col);
    }
    asm volatile("cp.async.commit_group;" ::: "memory");

    auto issueK = [&](int nt, int kc) {   // K chunk: 128 n-rows x 32 d (hi+lo)
        const int slot = kc & 1, k0 = kc * 32;
#pragma unroll
        for (int r = 0; r < 4; ++r) {
            const int idx = tid + r * 128;
            const int row = idx >> 2, col = (idx & 3) * 8;
            const size_t src = (size_t)(nt * 128 + row) * 128 + k0 + col;
            cpa16(kpl(slot, 0) + row * SSTR + col, Kh + src);
            cpa16(kpl(slot, 1) + row * SSTR + col, Kl + src);
        }
        asm volatile("cp.async.commit_group;" ::: "memory");
    };
    auto issueV = [&](int nt, int vc) {   // V s-chunk: 32 key-rows x 128 d
        const int slot = vc & 1;
#pragma unroll
        for (int r = 0; r < 4; ++r) {
            const int idx = tid + r * 128;
            const int row = idx >> 4, col = (idx & 15) * 8;
            cpa16(vpl(slot) + row * VSTR + col,
                  Vs + (size_t)(nt * 128 + vc * 32 + row) * 128 + col);
        }
        asm volatile("cp.async.commit_group;" ::: "memory");
    };

    issueK(0, 0);
    issueK(0, 1);

    // fused colsum reduction for this head (overlaps with cp.async)
    if (tid < 64) {
        float a = 0.f;
#pragma unroll
        for (int sc = 0; sc < 16; ++sc)
            a += g_ColPart[((size_t)h * 16 + sc) * 64 + tid];
        csum[tid] = a;
    }

    float c[16][4] = {};   // S tile: m16 x n128 per warp
    float o[16][4] = {};   // O tile: m16 x d128 per warp (persistent)
    const int lrow = lane & 15, lkh = (lane >> 4) * 8;
    const int qrow = (warp * 16 + lrow) * SSTR;

    for (int nt = 0; nt < 16; ++nt) {
        // ---- S phase: 4 d-chunks ----
#pragma unroll
        for (int kc = 0; kc < 4; ++kc) {
            asm volatile("cp.async.wait_group 1;" ::: "memory");
            __syncthreads();
            const int slot = kc & 1;
#pragma unroll
            for (int s = 0; s < 2; ++s) {
                const int ks = s * 16;
                uint32_t a0[4], a1[4];
                ldm4(a0, qpl(0, kc) + qrow + ks + lkh);
                ldm4(a1, qpl(1, kc) + qrow + ks + lkh);
#pragma unroll
                for (int nn = 0; nn < 8; ++nn) {
                    uint32_t bh[4];
                    ldm4(bh, kpl(slot, 0) + (nn * 16 + lrow) * SSTR + ks + lkh);
                    mma16816(c[2 * nn],     a0, bh[0], bh[2]);
                    mma16816(c[2 * nn + 1], a0, bh[1], bh[3]);
                    mma16816(c[2 * nn],     a1, bh[0], bh[2]);
                    mma16816(c[2 * nn + 1], a1, bh[1], bh[3]);
                    uint32_t bl[4];
                    ldm4(bl, kpl(slot, 1) + (nn * 16 + lrow) * SSTR + ks + lkh);
                    mma16816(c[2 * nn],     a0, bl[0], bl[2]);
                    mma16816(c[2 * nn + 1], a0, bl[1], bl[3]);
                }
            }
            __syncthreads();
            if      (kc == 0) issueK(nt, 2);
            else if (kc == 1) issueK(nt, 3);
            else if (kc == 2) issueV(nt, 0);
            else              issueV(nt, 1);
        }

        // ---- PV phase: 4 s-chunks of 32 keys ----
#pragma unroll
        for (int vc = 0; vc < 4; ++vc) {
            if (nt == 15 && vc == 3) asm volatile("cp.async.wait_group 0;" ::: "memory");
            else                     asm volatile("cp.async.wait_group 1;" ::: "memory");
            __syncthreads();
            const int slot = vc & 1;
#pragma unroll
            for (int s = 0; s < 2; ++s) {
                const int j = vc * 2 + s;      // k16-step 0..7 over n-tile
                uint32_t pa[4];                 // P A-frag from C tiles 2j, 2j+1
                pa[0] = sig2(c[2 * j][0],     c[2 * j][1]);
                pa[1] = sig2(c[2 * j][2],     c[2 * j][3]);
                pa[2] = sig2(c[2 * j + 1][0], c[2 * j + 1][1]);
                pa[3] = sig2(c[2 * j + 1][2], c[2 * j + 1][3]);
#pragma unroll
                for (int nn = 0; nn < 8; ++nn) {
                    uint32_t b[4];
                    ldm4t(b, vpl(slot) + (s * 16 + lrow) * VSTR + nn * 16 + lkh);
                    mma16816(o[2 * nn],     pa, b[0], b[1]);
                    mma16816(o[2 * nn + 1], pa, b[2], b[3]);
                }
            }
            __syncthreads();
            if      (vc == 0) issueV(nt, 2);
            else if (vc == 1) issueV(nt, 3);
            else if (vc == 2) { if (nt < 15) issueK(nt + 1, 0); }
            else              { if (nt < 15) issueK(nt + 1, 1); }
        }

#pragma unroll
        for (int j = 0; j < 16; ++j)
#pragma unroll
            for (int q = 0; q < 4; ++q) c[j][q] = 0.f;
    }

    // ---- epilogue: O -> g_Valshi (vals1 = colsum - O1) ----
#pragma unroll
    for (int j = 0; j < 16; ++j)
#pragma unroll
        for (int p = 0; p < 2; ++p) {
            const int m = m0 + warp * 16 + (lane >> 2) + p * 8;
            const int nl = j * 8 + (lane & 3) * 2;
            const int b = nl >> 6, d = nl & 63;
            float v0 = o[j][2 * p], v1 = o[j][2 * p + 1];
            if (b) {
                v0 = csum[d]     - v0;
                v1 = csum[d + 1] - v1;
            }
            *(__half2*)&g_Valshi[((size_t)(b * 2048 + m)) * 1024 + h * 64 + d] =
                __floats2half2_rn(v0, v1);
        }
}

// ---------------------------------------------------------------------------
// merged prep: blocks [0,4096) split x ; blocks [4096,8192) transpose+split W
// ---------------------------------------------------------------------------
__global__ __launch_bounds__(256) void prep_kernel(
    const float* __restrict__ x,
    const float* __restrict__ w0, const float* __restrict__ w1,
    const float* __restrict__ w2, const float* __restrict__ w3)
{
    __shared__ float t[32][33];
    if (blockIdx.x < 4096) {
        const size_t i = ((size_t)blockIdx.x * 256 + threadIdx.x) * 4;
        float4 v = *(const float4*)(x + i);
        splitstore(&g_xhi[i],     &g_xlo[i],     v.x, v.y);
        splitstore(&g_xhi[i + 2], &g_xlo[i + 2], v.z, v.w);
        return;
    }
    const int tb = blockIdx.x - 4096;
    const int z = tb >> 10, r = tb & 1023;
    const int bx = (r & 31) * 32, by = (r >> 5) * 32;
    const float* W = (z == 0) ? w0 : (z == 1) ? w1 : (z == 2) ? w2 : w3;
    const int tx = threadIdx.x & 31, ty8 = threadIdx.x >> 5;
#pragma unroll
    for (int s = 0; s < 4; ++s)
        t[ty8 + s * 8][tx] = W[(size_t)(by + ty8 + s * 8) * 1024 + bx + tx];
    __syncthreads();
    __half* Dh = g_wThi + (size_t)z * 1048576;
    __half* Dl = g_wTlo + (size_t)z * 1048576;
#pragma unroll
    for (int s = 0; s < 4; ++s) {
        const int ty = ty8 + s * 8;
        const float v = t[tx][ty];
        const size_t o = (size_t)(bx + ty) * 1024 + by + tx;
        __half h = __float2half_rn(v);
        Dh[o] = h;
        Dl[o] = __float2half_rn(v - __half2float(h));
    }
}

// ---------------------------------------------------------------------------
extern "C" void kernel_launch(void* const* d_in, const int* in_sizes, int n_in,
                              void* d_out, int out_size)
{
    const float* x  = (const float*)d_in[0];
    const float* wq = (const float*)d_in[1];
    const float* wk = (const float*)d_in[2];
    const float* wv = (const float*)d_in[3];
    const float* wo = (const float*)d_in[4];
    float* out = (float*)d_out;

    const int PB    = PLANEH * 2;                         // 10240 B / plane
    const int SM_QK = 2 * 4 * PB;                         //  81920 (3-term, 2-stage)
    const int SM_1T = 3 * 2 * PB;                         //  61440 (1-term, 3-stage)
    const int SM_FA = (20480 + 20480 + 8704) * 2 + 256;   //  99584 (fused attn + csum)

    cudaFuncSetAttribute(gemm_kernel<1024, 3, EPI_QK,  2, 2>, cudaFuncAttributeMaxDynamicSharedMemorySize, SM_QK);
    cudaFuncSetAttribute(gemm_kernel<1024, 1, EPI_V,   2, 3>, cudaFuncAttributeMaxDynamicSharedMemorySize, SM_1T);
    cudaFuncSetAttribute(gemm_kernel<1024, 1, EPI_OUT, 2, 3>, cudaFuncAttributeMaxDynamicSharedMemorySize, SM_1T);
    cudaFuncSetAttribute(fattn_kernel, cudaFuncAttributeMaxDynamicSharedMemorySize, SM_FA);

    prep_kernel<<<8192, 256>>>(x, wq, wk, wv, wo);

    gemm_kernel<1024, 3, EPI_QK, 2, 2><<<dim3(8, 32, 2), 256, SM_QK>>>(nullptr);
    gemm_kernel<1024, 1, EPI_V,  2, 3><<<dim3(8, 32, 1), 256, SM_1T>>>(nullptr);

    fattn_kernel<<<dim3(32, 16), 128, SM_FA>>>();

    gemm_kernel<1024, 1, EPI_OUT, 2, 3><<<dim3(8, 32, 1), 256, SM_1T>>>(out);
}

// round 16
// speedup vs baseline: 2.2335x; 1.0386x over previous
#include <cuda_runtime.h>
#include <cuda_fp16.h>
#include <cstdint>

// ---------------------------------------------------------------------------
// B=2,S=2048,D=1024,H=16,HD=64, scale=32. softmax over batch (B=2) ==
//   P     = sigmoid((Q0K0^T - Q1K1^T)/32)   per head [2048x2048]
//   vals0 = P @ V0 ;  vals1 = colsum(V1) - P @ V1
// fp16 mma.sync m16n8k16; hi/lo split planes:
//   Q/K proj: 3-term | fused score+PV (flash, V via ldmatrix.trans) |
//   V proj (+fused colsum partials), out: 1-term
// QKV projections merged in ONE launch (z dispatch) for wave packing.
// ---------------------------------------------------------------------------

__device__ __align__(128) __half g_xhi[4096 * 1024];
__device__ __align__(128) __half g_xlo[4096 * 1024];
__device__ __align__(128) __half g_wThi[4 * 1024 * 1024];   // [z][n][k]
__device__ __align__(128) __half g_wTlo[4 * 1024 * 1024];
__device__ __align__(128) __half g_Qhi[16 * 2048 * 128];    // [h][s][b*64+d]
__device__ __align__(128) __half g_Qlo[16 * 2048 * 128];
__device__ __align__(128) __half g_Khi[16 * 2048 * 128];    // K1 negated
__device__ __align__(128) __half g_Klo[16 * 2048 * 128];
__device__ __align__(128) __half g_V16[16 * 2048 * 128];    // fp16 V [h][s][b*64+d]
__device__ __align__(128) __half g_Valshi[4096 * 1024];     // [b*2048+q][h*64+d]
__device__ float g_ColPart[16 * 16 * 64];                   // [h][sc][d]

#define SSTR   40                 // halfs per smem row, 32-K chunks (+8 pad)
#define PLANEH (128 * SSTR)       // 5120 halfs / 10240 B
#define VSTR   136                // halfs per row for trans-read V chunks

// ---------------------------------------------------------------------------
static __device__ __forceinline__ void cpa16(const __half* dst_smem, const void* src) {
    uint32_t d = (uint32_t)__cvta_generic_to_shared(dst_smem);
    asm volatile("cp.async.cg.shared.global [%0], [%1], 16;" :: "r"(d), "l"(src));
}
static __device__ __forceinline__ void ldm4(uint32_t r[4], const void* p) {
    uint32_t a = (uint32_t)__cvta_generic_to_shared(p);
    asm volatile("ldmatrix.sync.aligned.m8n8.x4.shared.b16 {%0,%1,%2,%3}, [%4];"
                 : "=r"(r[0]), "=r"(r[1]), "=r"(r[2]), "=r"(r[3]) : "r"(a));
}
static __device__ __forceinline__ void ldm4t(uint32_t r[4], const void* p) {
    uint32_t a = (uint32_t)__cvta_generic_to_shared(p);
    asm volatile("ldmatrix.sync.aligned.m8n8.x4.trans.shared.b16 {%0,%1,%2,%3}, [%4];"
                 : "=r"(r[0]), "=r"(r[1]), "=r"(r[2]), "=r"(r[3]) : "r"(a));
}
static __device__ __forceinline__ void mma16816(float c[4], const uint32_t a[4],
                                                uint32_t b0, uint32_t b1) {
    asm volatile(
        "mma.sync.aligned.m16n8k16.row.col.f32.f16.f16.f32 "
        "{%0,%1,%2,%3}, {%4,%5,%6,%7}, {%8,%9}, {%0,%1,%2,%3};"
        : "+f"(c[0]), "+f"(c[1]), "+f"(c[2]), "+f"(c[3])
        : "r"(a[0]), "r"(a[1]), "r"(a[2]), "r"(a[3]), "r"(b0), "r"(b1));
}
static __device__ __forceinline__ void splitstore(__half* hp, __half* lp,
                                                  float v0, float v1) {
    __half h0 = __float2half_rn(v0), h1 = __float2half_rn(v1);
    *(__half2*)hp = __halves2half2(h0, h1);
    *(__half2*)lp = __halves2half2(__float2half_rn(v0 - __half2float(h0)),
                                   __float2half_rn(v1 - __half2float(h1)));
}
// sigmoid(S/32) pair -> packed fp16x2 (lo = first value)
static __device__ __forceinline__ uint32_t sig2(float f0, float f1) {
    const float NK = -0.04508422f;   // -log2(e)/32
    __half2 m2 = __floats2half2_rn(f0 * NK, f1 * NK);
    __half2 P2 = h2rcp(__hadd2(__float2half2_rn(1.0f), h2exp2(m2)));
    return *reinterpret_cast<uint32_t*>(&P2);
}

enum { EPI_QK = 0, EPI_V, EPI_OUT };

// ---------------------------------------------------------------------------
// 128x128 NT GEMM body (device fn), fp16 mma + ldmatrix, NSTG-stage cp.async.
// NTERM=3: Ahi*Bhi + Alo*Bhi + Ahi*Blo ; NTERM=1: A*Bhi
// EPI_V additionally emits deterministic colsum partials of batch-1 V rows.
// ---------------------------------------------------------------------------
template <int KTOT, int NTERM, int EPI, int NSTG>
static __device__ __forceinline__ void gemm_body(float* outp, __half* sm)
{
    const int NA = (NTERM == 3) ? 2 : 1;
    const int NB = (NTERM >= 2) ? 2 : 1;
    const int NT = NA + NB;

    const int tid = threadIdx.x, warp = tid >> 5, lane = tid & 31;
    const int wm = (warp & 3) * 32, wn = (warp >> 2) * 64;
    const int m0 = blockIdx.y * 128, n0 = blockIdx.x * 128, z = blockIdx.z;

    const __half *Ahi, *Alo = nullptr, *Bhi, *Blo = nullptr;
    int lda, ldb;
    if (EPI == EPI_QK) {
        Ahi = g_xhi; Alo = g_xlo; lda = 1024;
        Bhi = g_wThi + (size_t)z * 1048576; Blo = g_wTlo + (size_t)z * 1048576; ldb = 1024;
    } else if (EPI == EPI_V) {
        Ahi = g_xhi; lda = 1024;
        Bhi = g_wThi + (size_t)2 * 1048576; ldb = 1024;
    } else {
        Ahi = g_Valshi; lda = 1024;
        Bhi = g_wThi + (size_t)3 * 1048576; ldb = 1024;
    }

    auto plane = [&](int st, int pl) -> __half* { return sm + (st * NT + pl) * PLANEH; };

    auto load_stage = [&](int ch) {
        const int st = ch % NSTG, k0 = ch * 32;
#pragma unroll
        for (int r = 0; r < 2; ++r) {
            const int idx = tid + r * 256;
            const int row = idx >> 2, col = (idx & 3) * 8;
            cpa16(plane(st, 0) + row * SSTR + col, Ahi + (size_t)(m0 + row) * lda + k0 + col);
            if (NA == 2)
                cpa16(plane(st, 1) + row * SSTR + col, Alo + (size_t)(m0 + row) * lda + k0 + col);
            cpa16(plane(st, NA) + row * SSTR + col, Bhi + (size_t)(n0 + row) * ldb + k0 + col);
            if (NB == 2)
                cpa16(plane(st, NA + 1) + row * SSTR + col, Blo + (size_t)(n0 + row) * ldb + k0 + col);
        }
        asm volatile("cp.async.commit_group;" ::: "memory");
    };

    float c[2][8][4] = {};
    const int nCh = KTOT / 32;
    load_stage(0);
    if (NSTG == 3 && nCh > 1) load_stage(1);

    const int lrow = lane & 15, lkh = (lane >> 4) * 8;

    for (int ch = 0; ch < nCh; ++ch) {
        if (NSTG == 3) {
            if (ch + 1 < nCh) asm volatile("cp.async.wait_group 1;" ::: "memory");
            else              asm volatile("cp.async.wait_group 0;" ::: "memory");
            __syncthreads();
            if (ch + 2 < nCh) load_stage(ch + 2);
        } else {
            if (ch + 1 < nCh) {
                __syncthreads();
                load_stage(ch + 1);
                asm volatile("cp.async.wait_group 1;" ::: "memory");
            } else {
                asm volatile("cp.async.wait_group 0;" ::: "memory");
            }
            __syncthreads();
        }
        const int buf = ch % NSTG;

#pragma unroll
        for (int s = 0; s < 2; ++s) {
            const int ks = s * 16;
            uint32_t a[2][2][4];
#pragma unroll
            for (int pa = 0; pa < NA; ++pa)
#pragma unroll
                for (int mt = 0; mt < 2; ++mt)
                    ldm4(a[pa][mt], plane(buf, pa) + (wm + mt * 16 + lrow) * SSTR + ks + lkh);

            uint32_t bh[4][4];
#pragma unroll
            for (int np = 0; np < 4; ++np) {
                ldm4(bh[np], plane(buf, NA) + (wn + np * 16 + lrow) * SSTR + ks + lkh);
#pragma unroll
                for (int mt = 0; mt < 2; ++mt) {
                    mma16816(c[mt][2 * np],     a[0][mt], bh[np][0], bh[np][2]);
                    mma16816(c[mt][2 * np + 1], a[0][mt], bh[np][1], bh[np][3]);
                }
            }
            if (NA == 2) {
#pragma unroll
                for (int np = 0; np < 4; ++np)
#pragma unroll
                    for (int mt = 0; mt < 2; ++mt) {
                        mma16816(c[mt][2 * np],     a[1][mt], bh[np][0], bh[np][2]);
                        mma16816(c[mt][2 * np + 1], a[1][mt], bh[np][1], bh[np][3]);
                    }
            }
            if (NB == 2) {
#pragma unroll
                for (int np = 0; np < 4; ++np) {
                    uint32_t bl[4];
                    ldm4(bl, plane(buf, NA + 1) + (wn + np * 16 + lrow) * SSTR + ks + lkh);
#pragma unroll
                    for (int mt = 0; mt < 2; ++mt) {
                        mma16816(c[mt][2 * np],     a[0][mt], bl[0], bl[2]);
                        mma16816(c[mt][2 * np + 1], a[0][mt], bl[1], bl[3]);
                    }
                }
            }
        }
    }

    // ---- epilogue: m = m0+wm+mt*16+lane/4+p*8 ; n = n0+wn+nt*8+(lane%4)*2 ----
    float lc[8][2];
    if (EPI == EPI_V)
#pragma unroll
        for (int nt = 0; nt < 8; ++nt) { lc[nt][0] = 0.f; lc[nt][1] = 0.f; }

#pragma unroll
    for (int mt = 0; mt < 2; ++mt)
#pragma unroll
        for (int nt = 0; nt < 8; ++nt)
#pragma unroll
            for (int p = 0; p < 2; ++p) {
                const int m = m0 + wm + mt * 16 + (lane >> 2) + p * 8;
                const int nl = wn + nt * 8 + (lane & 3) * 2;
                float v0 = c[mt][nt][2 * p], v1 = c[mt][nt][2 * p + 1];

                if (EPI == EPI_QK) {
                    const int b = m >> 11, s = m & 2047;
                    const int n = n0 + nl, h = n >> 6, d = n & 63;
                    const size_t base = ((size_t)(h * 2048 + s)) * 128 + b * 64 + d;
                    if (z == 1 && b == 1) { v0 = -v0; v1 = -v1; }
                    __half* Dh = (z == 0) ? g_Qhi : g_Khi;
                    __half* Dl = (z == 0) ? g_Qlo : g_Klo;
                    splitstore(&Dh[base], &Dl[base], v0, v1);
                } else if (EPI == EPI_V) {
                    const int b = m >> 11, s = m & 2047;
                    const int n = n0 + nl, h = n >> 6, d = n & 63;
                    __half2 hv = __floats2half2_rn(v0, v1);
                    *(__half2*)&g_V16[((size_t)(h * 2048 + s)) * 128 + b * 64 + d] = hv;
                    lc[nt][0] += __half2float(__low2half(hv));
                    lc[nt][1] += __half2float(__high2half(hv));
                } else {
                    *(float2*)&outp[(size_t)m * 1024 + n0 + nl] = make_float2(v0, v1);
                }
            }

    // ---- fused colsum partials (batch-1 CTAs only; deterministic order) ----
    if (EPI == EPI_V) {
        float* colbuf = (float*)sm;   // [8 warps][128 cols]
        __syncthreads();
        if (blockIdx.y >= 16) {
#pragma unroll
            for (int nt = 0; nt < 8; ++nt)
#pragma unroll
                for (int j = 0; j < 2; ++j) {
                    float s = lc[nt][j];
                    s += __shfl_xor_sync(0xffffffffu, s, 4);
                    s += __shfl_xor_sync(0xffffffffu, s, 8);
                    s += __shfl_xor_sync(0xffffffffu, s, 16);
                    if ((lane >> 2) == 0)
                        colbuf[warp * 128 + wn + nt * 8 + (lane & 3) * 2 + j] = s;
                }
        }
        __syncthreads();
        if (blockIdx.y >= 16 && tid < 128) {
            const int col = tid, g = col >> 6;
            float s = colbuf[(g * 4 + 0) * 128 + col] + colbuf[(g * 4 + 1) * 128 + col]
                    + colbuf[(g * 4 + 2) * 128 + col] + colbuf[(g * 4 + 3) * 128 + col];
            const int n = n0 + col, h = n >> 6, d = n & 63;
            g_ColPart[((size_t)h * 16 + (blockIdx.y - 16)) * 64 + d] = s;
        }
    }
}

// merged QKV projection: z in {0,1} -> 3-term Q/K, z == 2 -> 1-term V
__global__ __launch_bounds__(256, 2) void qkv_kernel()
{
    extern __shared__ __align__(128) __half sm[];
    if (blockIdx.z == 2) gemm_body<1024, 1, EPI_V, 3>(nullptr, sm);
    else                 gemm_body<1024, 3, EPI_QK, 2>(nullptr, sm);
}

__global__ __launch_bounds__(256, 2) void out_kernel(float* outp)
{
    extern __shared__ __align__(128) __half sm[];
    gemm_body<1024, 1, EPI_OUT, 3>(outp, sm);
}

// ---------------------------------------------------------------------------
// Fused score+PV (flash style). Per CTA: 64 q-rows of one head.
// Colsum for this head reduced from partials in the prologue (smem csum).
// 128 threads = 4 warps, warp = 16 m-rows. smem 99584 B -> occ 2.
// ---------------------------------------------------------------------------
__global__ __launch_bounds__(128, 2) void fattn_kernel()
{
    extern __shared__ __align__(128) __half sm[];
    // Q: [2 planes][4 kc][64 x 40]  (20480 halfs)
    auto qpl = [&](int p, int kc) -> __half* { return sm + (p * 4 + kc) * 2560; };
    // K: [2 slots][2 planes][128 x 40] (20480 halfs)
    auto kpl = [&](int slot, int pl) -> __half* { return sm + 20480 + (slot * 2 + pl) * PLANEH; };
    // V: [2 slots][32 x 136] (8704 halfs)
    auto vpl = [&](int slot) -> __half* { return sm + 40960 + slot * (32 * VSTR); };
    float* csum = (float*)(sm + 49664);   // [64]

    const int tid = threadIdx.x, warp = tid >> 5, lane = tid & 31;
    const int h = blockIdx.y, m0 = blockIdx.x * 64;

    const __half* Qh = g_Qhi + ((size_t)h * 2048 + m0) * 128;
    const __half* Ql = g_Qlo + ((size_t)h * 2048 + m0) * 128;
    const __half* Kh = g_Khi + (size_t)h * 2048 * 128;
    const __half* Kl = g_Klo + (size_t)h * 2048 * 128;
    const __half* Vs = g_V16 + (size_t)h * 2048 * 128;   // [s][128]

    // group 0: resident Q (both planes, kc-split)
#pragma unroll
    for (int r = 0; r < 8; ++r) {
        const int idx = tid + r * 128;
        const int row = idx >> 4, col = (idx & 15) * 8;
        const int kc = col >> 5, cc = col & 31;
        cpa16(qpl(0, kc) + row * SSTR + cc, Qh + row * 128 + col);
        cpa16(qpl(1, kc) + row * SSTR + cc, Ql + row * 128 + col);
    }
    asm volatile("cp.async.commit_group;" ::: "memory");

    auto issueK = [&](int nt, int kc) {   // K chunk: 128 n-rows x 32 d (hi+lo)
        const int slot = kc & 1, k0 = kc * 32;
#pragma unroll
        for (int r = 0; r < 4; ++r) {
            const int idx = tid + r * 128;
            const int row = idx >> 2, col = (idx & 3) * 8;
            const size_t src = (size_t)(nt * 128 + row) * 128 + k0 + col;
            cpa16(kpl(slot, 0) + row * SSTR + col, Kh + src);
            cpa16(kpl(slot, 1) + row * SSTR + col, Kl + src);
        }
        asm volatile("cp.async.commit_group;" ::: "memory");
    };
    auto issueV = [&](int nt, int vc) {   // V s-chunk: 32 key-rows x 128 d
        const int slot = vc & 1;
#pragma unroll
        for (int r = 0; r < 4; ++r) {
            const int idx = tid + r * 128;
            const int row = idx >> 4, col = (idx & 15) * 8;
            cpa16(vpl(slot) + row * VSTR + col,
                  Vs + (size_t)(nt * 128 + vc * 32 + row) * 128 + col);
        }
        asm volatile("cp.async.commit_group;" ::: "memory");
    };

    issueK(0, 0);
    issueK(0, 1);

    // fused colsum reduction for this head (overlaps with cp.async)
    if (tid < 64) {
        float a = 0.f;
#pragma unroll
        for (int sc = 0; sc < 16; ++sc)
            a += g_ColPart[((size_t)h * 16 + sc) * 64 + tid];
        csum[tid] = a;
    }

    float c[16][4] = {};   // S tile: m16 x n128 per warp
    float o[16][4] = {};   // O tile: m16 x d128 per warp (persistent)
    const int lrow = lane & 15, lkh = (lane >> 4) * 8;
    const int qrow = (warp * 16 + lrow) * SSTR;

    for (int nt = 0; nt < 16; ++nt) {
        // ---- S phase: 4 d-chunks ----
#pragma unroll
        for (int kc = 0; kc < 4; ++kc) {
            asm volatile("cp.async.wait_group 1;" ::: "memory");
            __syncthreads();
            const int slot = kc & 1;
#pragma unroll
            for (int s = 0; s < 2; ++s) {
                const int ks = s * 16;
                uint32_t a0[4], a1[4];
                ldm4(a0, qpl(0, kc) + qrow + ks + lkh);
                ldm4(a1, qpl(1, kc) + qrow + ks + lkh);
#pragma unroll
                for (int nn = 0; nn < 8; ++nn) {
                    uint32_t bh[4];
                    ldm4(bh, kpl(slot, 0) + (nn * 16 + lrow) * SSTR + ks + lkh);
                    mma16816(c[2 * nn],     a0, bh[0], bh[2]);
                    mma16816(c[2 * nn + 1], a0, bh[1], bh[3]);
                    mma16816(c[2 * nn],     a1, bh[0], bh[2]);
                    mma16816(c[2 * nn + 1], a1, bh[1], bh[3]);
                    uint32_t bl[4];
                    ldm4(bl, kpl(slot, 1) + (nn * 16 + lrow) * SSTR + ks + lkh);
                    mma16816(c[2 * nn],     a0, bl[0], bl[2]);
                    mma16816(c[2 * nn + 1], a0, bl[1], bl[3]);
                }
            }
            __syncthreads();
            if      (kc == 0) issueK(nt, 2);
            else if (kc == 1) issueK(nt, 3);
            else if (kc == 2) issueV(nt, 0);
            else              issueV(nt, 1);
        }

        // ---- PV phase: 4 s-chunks of 32 keys ----
#pragma unroll
        for (int vc = 0; vc < 4; ++vc) {
            if (nt == 15 && vc == 3) asm volatile("cp.async.wait_group 0;" ::: "memory");
            else                     asm volatile("cp.async.wait_group 1;" ::: "memory");
            __syncthreads();
            const int slot = vc & 1;
#pragma unroll
            for (int s = 0; s < 2; ++s) {
                const int j = vc * 2 + s;      // k16-step 0..7 over n-tile
                uint32_t pa[4];                 // P A-frag from C tiles 2j, 2j+1
                pa[0] = sig2(c[2 * j][0],     c[2 * j][1]);
                pa[1] = sig2(c[2 * j][2],     c[2 * j][3]);
                pa[2] = sig2(c[2 * j + 1][0], c[2 * j + 1][1]);
                pa[3] = sig2(c[2 * j + 1][2], c[2 * j + 1][3]);
#pragma unroll
                for (int nn = 0; nn < 8; ++nn) {
                    uint32_t b[4];
                    ldm4t(b, vpl(slot) + (s * 16 + lrow) * VSTR + nn * 16 + lkh);
                    mma16816(o[2 * nn],     pa, b[0], b[1]);
                    mma16816(o[2 * nn + 1], pa, b[2], b[3]);
                }
            }
            __syncthreads();
            if      (vc == 0) issueV(nt, 2);
            else if (vc == 1) issueV(nt, 3);
            else if (vc == 2) { if (nt < 15) issueK(nt + 1, 0); }
            else              { if (nt < 15) issueK(nt + 1, 1); }
        }

#pragma unroll
        for (int j = 0; j < 16; ++j)
#pragma unroll
            for (int q = 0; q < 4; ++q) c[j][q] = 0.f;
    }

    // ---- epilogue: O -> g_Valshi (vals1 = colsum - O1) ----
#pragma unroll
    for (int j = 0; j < 16; ++j)
#pragma unroll
        for (int p = 0; p < 2; ++p) {
            const int m = m0 + warp * 16 + (lane >> 2) + p * 8;
            const int nl = j * 8 + (lane & 3) * 2;
            const int b = nl >> 6, d = nl & 63;
            float v0 = o[j][2 * p], v1 = o[j][2 * p + 1];
            if (b) {
                v0 = csum[d]     - v0;
                v1 = csum[d + 1] - v1;
            }
            *(__half2*)&g_Valshi[((size_t)(b * 2048 + m)) * 1024 + h * 64 + d] =
                __floats2half2_rn(v0, v1);
        }
}

// ---------------------------------------------------------------------------
// merged prep: blocks [0,4096) split x ; blocks [4096,8192) transpose+split W
// ---------------------------------------------------------------------------
__global__ __launch_bounds__(256) void prep_kernel(
    const float* __restrict__ x,
    const float* __restrict__ w0, const float* __restrict__ w1,
    const float* __restrict__ w2, const float* __restrict__ w3)
{
    __shared__ float t[32][33];
    if (blockIdx.x < 4096) {
        const size_t i = ((size_t)blockIdx.x * 256 + threadIdx.x) * 4;
        float4 v = *(const float4*)(x + i);
        splitstore(&g_xhi[i],     &g_xlo[i],     v.x, v.y);
        splitstore(&g_xhi[i + 2], &g_xlo[i + 2], v.z, v.w);
        return;
    }
    const int tb = blockIdx.x - 4096;
    const int z = tb >> 10, r = tb & 1023;
    const int bx = (r & 31) * 32, by = (r >> 5) * 32;
    const float* W = (z == 0) ? w0 : (z == 1) ? w1 : (z == 2) ? w2 : w3;
    const int tx = threadIdx.x & 31, ty8 = threadIdx.x >> 5;
#pragma unroll
    for (int s = 0; s < 4; ++s)
        t[ty8 + s * 8][tx] = W[(size_t)(by + ty8 + s * 8) * 1024 + bx + tx];
    __syncthreads();
    __half* Dh = g_wThi + (size_t)z * 1048576;
    __half* Dl = g_wTlo + (size_t)z * 1048576;
#pragma unroll
    for (int s = 0; s < 4; ++s) {
        const int ty = ty8 + s * 8;
        const float v = t[tx][ty];
        const size_t o = (size_t)(bx + ty) * 1024 + by + tx;
        __half h = __float2half_rn(v);
        Dh[o] = h;
        Dl[o] = __float2half_rn(v - __half2float(h));
    }
}

// ---------------------------------------------------------------------------
extern "C" void kernel_launch(void* const* d_in, const int* in_sizes, int n_in,
                              void* d_out, int out_size)
{
    const float* x  = (const float*)d_in[0];
    const float* wq = (const float*)d_in[1];
    const float* wk = (const float*)d_in[2];
    const float* wv = (const float*)d_in[3];
    const float* wo = (const float*)d_in[4];
    float* out = (float*)d_out;

    const int PB     = PLANEH * 2;                        // 10240 B / plane
    const int SM_QKV = 2 * 4 * PB;                        //  81920 (max of both paths)
    const int SM_1T  = 3 * 2 * PB;                        //  61440 (1-term, 3-stage)
    const int SM_FA  = (20480 + 20480 + 8704) * 2 + 256;  //  99584 (fused attn + csum)

    cudaFuncSetAttribute(qkv_kernel,   cudaFuncAttributeMaxDynamicSharedMemorySize, SM_QKV);
    cudaFuncSetAttribute(out_kernel,   cudaFuncAttributeMaxDynamicSharedMemorySize, SM_1T);
    cudaFuncSetAttribute(fattn_kernel, cudaFuncAttributeMaxDynamicSharedMemorySize, SM_FA);

    prep_kernel<<<8192, 256>>>(x, wq, wk, wv, wo);

    qkv_kernel<<<dim3(8, 32, 3), 256, SM_QKV>>>();

    fattn_kernel<<<dim3(32, 16), 128, SM_FA>>>();

    out_kernel<<<dim3(8, 32, 1), 256, SM_1T>>>(out);
}